// round 1
// baseline (speedup 1.0000x reference)
#include <cuda_runtime.h>
#include <math.h>

#define T_ 8
#define NT_ 12288
#define D_ 256
#define NN_ 8192
#define NS_ 32768
#define CL_ 16
#define CD_ 64
#define CHUNK_ 2048
#define H_ 128

// Scratch (device globals; zero-initialized at load; invariants maintained by cleanup)
__device__ float g_stats[T_ * NN_ * 2];                 // mean,rstd per input row
__device__ float g_pre1[(size_t)T_ * NS_ * H_];         // scatter accumulator (134 MB)
__device__ int   g_cnt[T_ * NS_];                       // per-slot contribution count
__device__ float g_S[T_ * CL_ * H_];                    // per-chunk gelu sums
__device__ float g_dec[T_ * CL_ * D_];                  // decoded vectors

__device__ __forceinline__ float geluf(float v) {
    return 0.5f * v * (1.0f + erff(v * 0.70710678118654752440f));
}

__device__ __forceinline__ unsigned long long packdup(float a) {
    unsigned long long r;
    asm("mov.b64 %0, {%1, %1};" : "=l"(r) : "f"(a));
    return r;
}
__device__ __forceinline__ unsigned long long fma2(unsigned long long a, unsigned long long b,
                                                   unsigned long long c) {
    unsigned long long d;
    asm("fma.rn.f32x2 %0, %1, %2, %3;" : "=l"(d) : "l"(a), "l"(b), "l"(c));
    return d;
}
__device__ __forceinline__ void unpack2(unsigned long long v, float& lo, float& hi) {
    asm("mov.b64 {%0, %1}, %2;" : "=f"(lo), "=f"(hi) : "l"(v));
}
__device__ __forceinline__ void red4(float* p, float a, float b, float c, float d) {
    asm volatile("red.global.add.v4.f32 [%0], {%1,%2,%3,%4};"
                 :: "l"(p), "f"(a), "f"(b), "f"(c), "f"(d) : "memory");
}

// ---------------------------------------------------------------------------
// K1: per-row LN stats (mean, rstd) for the first 8192 tokens of each t
// ---------------------------------------------------------------------------
__global__ void k_stats(const float* __restrict__ x) {
    int warp = threadIdx.x >> 5, lane = threadIdx.x & 31;
    int row = blockIdx.x * 8 + warp;             // 0..65535
    int t = row >> 13, i = row & (NN_ - 1);
    const float4* p = reinterpret_cast<const float4*>(x) + ((size_t)t * NT_ + i) * (D_ / 4);
    float4 a = p[lane], b = p[lane + 32];
    float s = a.x + a.y + a.z + a.w + b.x + b.y + b.z + b.w;
    float q = a.x * a.x + a.y * a.y + a.z * a.z + a.w * a.w +
              b.x * b.x + b.y * b.y + b.z * b.z + b.w * b.w;
    #pragma unroll
    for (int m = 16; m; m >>= 1) {
        s += __shfl_xor_sync(0xffffffffu, s, m);
        q += __shfl_xor_sync(0xffffffffu, q, m);
    }
    if (lane == 0) {
        float mean = s * (1.0f / 256.0f);
        float var = q * (1.0f / 256.0f) - mean * mean;
        g_stats[2 * row] = mean;
        g_stats[2 * row + 1] = rsqrtf(var + 1e-5f);
    }
}

// ---------------------------------------------------------------------------
// K2: fused LN-apply + GEMM1 (65536x128, K=256, fp32 via fma.f32x2) + scatter
// ---------------------------------------------------------------------------
__global__ void __launch_bounds__(256, 2)
k_gemm(const float* __restrict__ x, const int* __restrict__ indices,
       const float* __restrict__ lng, const float* __restrict__ lnb,
       const float* __restrict__ w1) {
    __shared__ __align__(16) float as[16][132];   // A tile [k][row], padded
    __shared__ __align__(16) float ws[16][128];   // W tile [k][col]
    __shared__ float2 sstat[128];

    int tid = threadIdx.x;
    int rowBase = blockIdx.x * 128;               // global projected row
    int t = rowBase >> 13;
    int iBase = rowBase & (NN_ - 1);

    for (int r = tid; r < 128; r += 256)
        sstat[r] = reinterpret_cast<const float2*>(g_stats)[rowBase + r];
    __syncthreads();

    unsigned long long acc[8][4];
    #pragma unroll
    for (int r = 0; r < 8; r++)
        #pragma unroll
        for (int c = 0; c < 4; c++) acc[r][c] = 0ull;

    int tx = tid & 15, ty = tid >> 4;             // 16x16 thread grid, 8x8 tiles
    const float4* x4 = reinterpret_cast<const float4*>(x) + ((size_t)t * NT_ + iBase) * (D_ / 4);
    const float4* w14 = reinterpret_cast<const float4*>(w1);
    const float4* g4p = reinterpret_cast<const float4*>(lng);
    const float4* b4p = reinterpret_cast<const float4*>(lnb);

    for (int kt = 0; kt < 16; kt++) {
        int k0q = kt * 4;                          // quad offset into D
        #pragma unroll
        for (int j = 0; j < 2; j++) {
            int idx = tid + j * 256;
            int r = idx >> 2, kq = idx & 3;
            float4 v = x4[r * 64 + k0q + kq];
            float2 st = sstat[r];
            float4 gg = __ldg(g4p + k0q + kq);
            float4 bb = __ldg(b4p + k0q + kq);
            int kk = kq * 4;
            as[kk + 0][r] = (v.x - st.x) * st.y * gg.x + bb.x;
            as[kk + 1][r] = (v.y - st.x) * st.y * gg.y + bb.y;
            as[kk + 2][r] = (v.z - st.x) * st.y * gg.z + bb.z;
            as[kk + 3][r] = (v.w - st.x) * st.y * gg.w + bb.w;
        }
        #pragma unroll
        for (int j = 0; j < 2; j++) {
            int idx = tid + j * 256;
            int kk = idx >> 5, cq = idx & 31;
            reinterpret_cast<float4*>(ws[kk])[cq] = w14[(kt * 16 + kk) * 32 + cq];
        }
        __syncthreads();
        #pragma unroll
        for (int kk = 0; kk < 16; kk++) {
            float4 a0 = *reinterpret_cast<const float4*>(&as[kk][ty * 8]);
            float4 a1 = *reinterpret_cast<const float4*>(&as[kk][ty * 8 + 4]);
            const unsigned long long* wp =
                reinterpret_cast<const unsigned long long*>(&ws[kk][tx * 8]);
            unsigned long long bd0 = wp[0], bd1 = wp[1], bd2 = wp[2], bd3 = wp[3];
            unsigned long long ad[8] = {packdup(a0.x), packdup(a0.y), packdup(a0.z), packdup(a0.w),
                                        packdup(a1.x), packdup(a1.y), packdup(a1.z), packdup(a1.w)};
            #pragma unroll
            for (int r = 0; r < 8; r++) {
                acc[r][0] = fma2(ad[r], bd0, acc[r][0]);
                acc[r][1] = fma2(ad[r], bd1, acc[r][1]);
                acc[r][2] = fma2(ad[r], bd2, acc[r][2]);
                acc[r][3] = fma2(ad[r], bd3, acc[r][3]);
            }
        }
        __syncthreads();
    }

    // Epilogue: scatter-add z rows into pre1[slot], bump slot counts
    const int* idxp = indices + t * NN_;
    #pragma unroll
    for (int r = 0; r < 8; r++) {
        int i = iBase + ty * 8 + r;
        int slot = idxp[i];
        float* dst = g_pre1 + ((size_t)t * NS_ + slot) * H_ + tx * 8;
        float f0, f1, f2, f3, f4, f5, f6, f7;
        unpack2(acc[r][0], f0, f1);
        unpack2(acc[r][1], f2, f3);
        unpack2(acc[r][2], f4, f5);
        unpack2(acc[r][3], f6, f7);
        red4(dst, f0, f1, f2, f3);
        red4(dst + 4, f4, f5, f6, f7);
        if (tx == 0) atomicAdd(&g_cnt[t * NS_ + slot], 1);
    }
}

// ---------------------------------------------------------------------------
// K3: per-chunk sum of gelu(pre1 + b1), skipping untouched (zero) slots;
//     zero slots contribute gelu(b1) analytically.
// ---------------------------------------------------------------------------
__global__ void k_chunk(const float* __restrict__ b1) {
    __shared__ float part[8][128];
    __shared__ int zcs[8];
    int tid = threadIdx.x;
    int nl = tid >> 5, cg = tid & 31;
    int t = blockIdx.x >> 4, c = blockIdx.x & 15;

    float4 b1v = reinterpret_cast<const float4*>(b1)[cg];
    float4 acc = make_float4(0.f, 0.f, 0.f, 0.f);
    int zc = 0;
    const int* cp = g_cnt + t * NS_ + c * CHUNK_;
    const float4* base =
        reinterpret_cast<const float4*>(g_pre1 + ((size_t)t * NS_ + c * CHUNK_) * H_);
    for (int n = nl; n < CHUNK_; n += 8) {
        if (cp[n]) {
            float4 v = base[n * 32 + cg];
            acc.x += geluf(v.x + b1v.x);
            acc.y += geluf(v.y + b1v.y);
            acc.z += geluf(v.z + b1v.z);
            acc.w += geluf(v.w + b1v.w);
        } else {
            zc++;
        }
    }
    part[nl][cg * 4 + 0] = acc.x;
    part[nl][cg * 4 + 1] = acc.y;
    part[nl][cg * 4 + 2] = acc.z;
    part[nl][cg * 4 + 3] = acc.w;
    if (cg == 0) zcs[nl] = zc;
    __syncthreads();
    if (tid < 128) {
        float s = 0.f;
        int z = 0;
        #pragma unroll
        for (int w = 0; w < 8; w++) { s += part[w][tid]; z += zcs[w]; }
        g_S[(t * CL_ + c) * H_ + tid] = s + (float)z * geluf(b1[tid]);
    }
}

// ---------------------------------------------------------------------------
// K4: finalize per t: comp = S@w2 + CHUNK*b2 ; LN(1024) ; per-chunk LN(64) ;
//     decoder MLP -> g_dec (16 rows of 256 per t)
// ---------------------------------------------------------------------------
__global__ void k_final(const float* __restrict__ w2, const float* __restrict__ b2,
                        const float* __restrict__ lnfg, const float* __restrict__ lnfb,
                        const float* __restrict__ lndg, const float* __restrict__ lndb,
                        const float* __restrict__ dw1, const float* __restrict__ db1,
                        const float* __restrict__ dw2, const float* __restrict__ db2) {
    __shared__ float sS[CL_ * H_];          // 2048
    __shared__ float sc[CL_ * CD_];         // 1024
    __shared__ float t2s[CL_ * CD_];        // 1024
    __shared__ __align__(16) float d1t[H_ * CL_];  // 2048, [k][c]
    __shared__ float redbuf[16];
    __shared__ float bcast[2];

    int tid = threadIdx.x, lane = tid & 31, warp = tid >> 5;
    int t = blockIdx.x;

    for (int o = tid; o < CL_ * H_; o += 256) sS[o] = g_S[t * CL_ * H_ + o];
    __syncthreads();

    // comp = S @ w2 + CHUNK*b2
    {
        int jj = tid & 63, cg = tid >> 6;   // cg in 0..3; thread covers chunks cg, cg+4, cg+8, cg+12
        float a0 = 0.f, a1 = 0.f, a2 = 0.f, a3 = 0.f;
        for (int k = 0; k < H_; k++) {
            float w = w2[k * 64 + jj];
            a0 += sS[(cg) * H_ + k] * w;
            a1 += sS[(cg + 4) * H_ + k] * w;
            a2 += sS[(cg + 8) * H_ + k] * w;
            a3 += sS[(cg + 12) * H_ + k] * w;
        }
        float bb = (float)CHUNK_ * b2[jj];
        sc[(cg) * 64 + jj] = a0 + bb;
        sc[(cg + 4) * 64 + jj] = a1 + bb;
        sc[(cg + 8) * 64 + jj] = a2 + bb;
        sc[(cg + 12) * 64 + jj] = a3 + bb;
    }
    __syncthreads();

    // LN over 1024 (lnf)
    float s = 0.f, q = 0.f;
    for (int o = tid; o < 1024; o += 256) { float v = sc[o]; s += v; q += v * v; }
    #pragma unroll
    for (int m = 16; m; m >>= 1) {
        s += __shfl_xor_sync(0xffffffffu, s, m);
        q += __shfl_xor_sync(0xffffffffu, q, m);
    }
    if (lane == 0) { redbuf[warp] = s; redbuf[8 + warp] = q; }
    __syncthreads();
    if (tid == 0) {
        float S2 = 0.f, Q2 = 0.f;
        #pragma unroll
        for (int w = 0; w < 8; w++) { S2 += redbuf[w]; Q2 += redbuf[8 + w]; }
        float m = S2 * (1.0f / 1024.0f);
        float var = Q2 * (1.0f / 1024.0f) - m * m;
        bcast[0] = m;
        bcast[1] = rsqrtf(var + 1e-5f);
    }
    __syncthreads();
    float m1 = bcast[0], rs1 = bcast[1];
    for (int o = tid; o < 1024; o += 256) sc[o] = (sc[o] - m1) * rs1 * lnfg[o] + lnfb[o];
    __syncthreads();

    // per-chunk LN over 64 (lnd) — each warp handles 2 chunks
    #pragma unroll
    for (int gi = 0; gi < 2; gi++) {
        int g = warp * 2 + gi;
        float v0 = sc[g * 64 + lane], v1 = sc[g * 64 + 32 + lane];
        float gs = v0 + v1, gq = v0 * v0 + v1 * v1;
        #pragma unroll
        for (int mm = 16; mm; mm >>= 1) {
            gs += __shfl_xor_sync(0xffffffffu, gs, mm);
            gq += __shfl_xor_sync(0xffffffffu, gq, mm);
        }
        float gm = gs * (1.0f / 64.0f);
        float gv = gq * (1.0f / 64.0f) - gm * gm;
        float grs = rsqrtf(gv + 1e-5f);
        t2s[g * 64 + lane] = (v0 - gm) * grs * lndg[lane] + lndb[lane];
        t2s[g * 64 + 32 + lane] = (v1 - gm) * grs * lndg[lane + 32] + lndb[lane + 32];
    }
    __syncthreads();

    // dec1 = gelu(t2 @ dw1 + db1), stored transposed d1t[k][c]
    {
        int kk = tid & 127;
        int ch = tid >> 7;  // 0..1
        float a[8];
        float b0 = db1[kk];
        #pragma unroll
        for (int u = 0; u < 8; u++) a[u] = b0;
        for (int j = 0; j < 64; j++) {
            float w = dw1[j * 128 + kk];
            #pragma unroll
            for (int u = 0; u < 8; u++) a[u] += t2s[(ch + u * 2) * 64 + j] * w;
        }
        #pragma unroll
        for (int u = 0; u < 8; u++) d1t[kk * 16 + (ch + u * 2)] = geluf(a[u]);
    }
    __syncthreads();

    // decoded[c][dd] = d1[c] @ dw2[:,dd] + db2[dd]; thread dd = tid
    {
        float o[16];
        float bb = db2[tid];
        #pragma unroll
        for (int c = 0; c < 16; c++) o[c] = bb;
        for (int k = 0; k < 128; k++) {
            float w = dw2[k * 256 + tid];
            const float4* dp = reinterpret_cast<const float4*>(&d1t[k * 16]);
            float4 q0 = dp[0], q1 = dp[1], q2 = dp[2], q3 = dp[3];
            o[0] += q0.x * w;  o[1] += q0.y * w;  o[2] += q0.z * w;  o[3] += q0.w * w;
            o[4] += q1.x * w;  o[5] += q1.y * w;  o[6] += q1.z * w;  o[7] += q1.w * w;
            o[8] += q2.x * w;  o[9] += q2.y * w;  o[10] += q2.z * w; o[11] += q2.w * w;
            o[12] += q3.x * w; o[13] += q3.y * w; o[14] += q3.z * w; o[15] += q3.w * w;
        }
        #pragma unroll
        for (int c = 0; c < 16; c++) g_dec[(t * CL_ + c) * D_ + tid] = o[c];
    }
}

// ---------------------------------------------------------------------------
// K5: output gather (rows < 8192: broadcast decoded chunk row; else zeros)
// ---------------------------------------------------------------------------
__global__ void k_gather(const int* __restrict__ indices, float4* __restrict__ out) {
    int idx = blockIdx.x * 256 + threadIdx.x;   // over T*NT*64 float4s
    int r = idx >> 6, q = idx & 63;
    int t = r / NT_;
    int i = r - t * NT_;
    float4 v;
    if (i < NN_) {
        int c = indices[t * NN_ + i] >> 11;     // chunk = slot / 2048
        v = reinterpret_cast<const float4*>(g_dec)[(t * CL_ + c) * 64 + q];
    } else {
        v = make_float4(0.f, 0.f, 0.f, 0.f);
    }
    out[idx] = v;
}

// ---------------------------------------------------------------------------
// K6: restore invariants — zero touched pre1 rows and counts
// ---------------------------------------------------------------------------
__global__ void k_cleanup() {
    int gw = (blockIdx.x * 256 + threadIdx.x) >> 5;
    int lane = threadIdx.x & 31;
    int nw = (gridDim.x * 256) >> 5;
    float4 z = make_float4(0.f, 0.f, 0.f, 0.f);
    for (int row = gw; row < T_ * NS_; row += nw) {
        if (g_cnt[row]) {
            float4* p = reinterpret_cast<float4*>(g_pre1 + (size_t)row * H_);
            p[lane] = z;
            if (lane == 0) g_cnt[row] = 0;
        }
    }
}

extern "C" void kernel_launch(void* const* d_in, const int* in_sizes, int n_in,
                              void* d_out, int out_size) {
    const float* x    = (const float*)d_in[0];
    const int*   ind  = (const int*)d_in[1];
    const float* ln1g = (const float*)d_in[2];
    const float* ln1b = (const float*)d_in[3];
    const float* w1   = (const float*)d_in[4];
    const float* b1   = (const float*)d_in[5];
    const float* w2   = (const float*)d_in[6];
    const float* b2   = (const float*)d_in[7];
    const float* lnfg = (const float*)d_in[8];
    const float* lnfb = (const float*)d_in[9];
    const float* lndg = (const float*)d_in[10];
    const float* lndb = (const float*)d_in[11];
    const float* dw1  = (const float*)d_in[12];
    const float* db1  = (const float*)d_in[13];
    const float* dw2  = (const float*)d_in[14];
    const float* db2  = (const float*)d_in[15];

    k_stats<<<T_ * NN_ / 8, 256>>>(x);
    k_gemm<<<T_ * NN_ / 128, 256>>>(x, ind, ln1g, ln1b, w1);
    k_chunk<<<T_ * CL_, 256>>>(b1);
    k_final<<<T_, 256>>>(w2, b2, lnfg, lnfb, lndg, lndb, dw1, db1, dw2, db2);
    k_gather<<<(T_ * NT_ * 64) / 256, 256>>>(ind, (float4*)d_out);
    k_cleanup<<<2048, 256>>>();
}

// round 2
// speedup vs baseline: 1.2202x; 1.2202x over previous
#include <cuda_runtime.h>
#include <math.h>

#define T_ 8
#define NT_ 12288
#define D_ 256
#define NN_ 8192
#define NS_ 32768
#define CL_ 16
#define CD_ 64
#define CHUNK_ 2048
#define H_ 128

// Scratch (device globals; zero-initialized at load; pre1/cnt invariants restored by k_chunk)
__device__ float g_stats[T_ * NN_ * 2];                 // mean,rstd per input row
__device__ float g_pre1[(size_t)T_ * NS_ * H_];         // scatter accumulator (134 MB)
__device__ int   g_cnt[T_ * NS_];                       // per-slot contribution count
__device__ float g_S[T_ * CL_ * H_];                    // per-chunk gelu sums
__device__ float g_t2[T_ * CL_ * CD_];                  // post-LN chunk vectors
__device__ float g_dec[T_ * CL_ * D_];                  // decoded vectors

__device__ __forceinline__ float geluf(float v) {
    return 0.5f * v * (1.0f + erff(v * 0.70710678118654752440f));
}

__device__ __forceinline__ unsigned long long packdup(float a) {
    unsigned long long r;
    asm("mov.b64 %0, {%1, %1};" : "=l"(r) : "f"(a));
    return r;
}
__device__ __forceinline__ unsigned long long fma2(unsigned long long a, unsigned long long b,
                                                   unsigned long long c) {
    unsigned long long d;
    asm("fma.rn.f32x2 %0, %1, %2, %3;" : "=l"(d) : "l"(a), "l"(b), "l"(c));
    return d;
}
__device__ __forceinline__ void unpack2(unsigned long long v, float& lo, float& hi) {
    asm("mov.b64 {%0, %1}, %2;" : "=f"(lo), "=f"(hi) : "l"(v));
}
__device__ __forceinline__ void red4(float* p, float a, float b, float c, float d) {
    asm volatile("red.global.add.v4.f32 [%0], {%1,%2,%3,%4};"
                 :: "l"(p), "f"(a), "f"(b), "f"(c), "f"(d) : "memory");
}

// ---------------------------------------------------------------------------
// K1: per-row LN stats (mean, rstd) for the first 8192 tokens of each t
// ---------------------------------------------------------------------------
__global__ void k_stats(const float* __restrict__ x) {
    int warp = threadIdx.x >> 5, lane = threadIdx.x & 31;
    int row = blockIdx.x * 8 + warp;             // 0..65535
    int t = row >> 13, i = row & (NN_ - 1);
    const float4* p = reinterpret_cast<const float4*>(x) + ((size_t)t * NT_ + i) * (D_ / 4);
    float4 a = p[lane], b = p[lane + 32];
    float s = a.x + a.y + a.z + a.w + b.x + b.y + b.z + b.w;
    float q = a.x * a.x + a.y * a.y + a.z * a.z + a.w * a.w +
              b.x * b.x + b.y * b.y + b.z * b.z + b.w * b.w;
    #pragma unroll
    for (int m = 16; m; m >>= 1) {
        s += __shfl_xor_sync(0xffffffffu, s, m);
        q += __shfl_xor_sync(0xffffffffu, q, m);
    }
    if (lane == 0) {
        float mean = s * (1.0f / 256.0f);
        float var = q * (1.0f / 256.0f) - mean * mean;
        g_stats[2 * row] = mean;
        g_stats[2 * row + 1] = rsqrtf(var + 1e-5f);
    }
}

// ---------------------------------------------------------------------------
// K2: fused LN-apply + GEMM1 (65536x128, K=256, fp32 via fma.f32x2) + scatter
// ---------------------------------------------------------------------------
__global__ void __launch_bounds__(256, 2)
k_gemm(const float* __restrict__ x, const int* __restrict__ indices,
       const float* __restrict__ lng, const float* __restrict__ lnb,
       const float* __restrict__ w1) {
    __shared__ __align__(16) float as[16][132];   // A tile [k][row], padded
    __shared__ __align__(16) float ws[16][128];   // W tile [k][col]
    __shared__ float2 sstat[128];

    int tid = threadIdx.x;
    int rowBase = blockIdx.x * 128;               // global projected row
    int t = rowBase >> 13;
    int iBase = rowBase & (NN_ - 1);

    for (int r = tid; r < 128; r += 256)
        sstat[r] = reinterpret_cast<const float2*>(g_stats)[rowBase + r];
    __syncthreads();

    unsigned long long acc[8][4];
    #pragma unroll
    for (int r = 0; r < 8; r++)
        #pragma unroll
        for (int c = 0; c < 4; c++) acc[r][c] = 0ull;

    int tx = tid & 15, ty = tid >> 4;             // 16x16 thread grid, 8x8 tiles
    const float4* x4 = reinterpret_cast<const float4*>(x) + ((size_t)t * NT_ + iBase) * (D_ / 4);
    const float4* w14 = reinterpret_cast<const float4*>(w1);
    const float4* g4p = reinterpret_cast<const float4*>(lng);
    const float4* b4p = reinterpret_cast<const float4*>(lnb);

    for (int kt = 0; kt < 16; kt++) {
        int k0q = kt * 4;                          // quad offset into D
        #pragma unroll
        for (int j = 0; j < 2; j++) {
            int idx = tid + j * 256;
            int r = idx >> 2, kq = idx & 3;
            float4 v = x4[r * 64 + k0q + kq];
            float2 st = sstat[r];
            float4 gg = __ldg(g4p + k0q + kq);
            float4 bb = __ldg(b4p + k0q + kq);
            int kk = kq * 4;
            as[kk + 0][r] = (v.x - st.x) * st.y * gg.x + bb.x;
            as[kk + 1][r] = (v.y - st.x) * st.y * gg.y + bb.y;
            as[kk + 2][r] = (v.z - st.x) * st.y * gg.z + bb.z;
            as[kk + 3][r] = (v.w - st.x) * st.y * gg.w + bb.w;
        }
        #pragma unroll
        for (int j = 0; j < 2; j++) {
            int idx = tid + j * 256;
            int kk = idx >> 5, cq = idx & 31;
            reinterpret_cast<float4*>(ws[kk])[cq] = w14[(kt * 16 + kk) * 32 + cq];
        }
        __syncthreads();
        #pragma unroll
        for (int kk = 0; kk < 16; kk++) {
            float4 a0 = *reinterpret_cast<const float4*>(&as[kk][ty * 8]);
            float4 a1 = *reinterpret_cast<const float4*>(&as[kk][ty * 8 + 4]);
            const unsigned long long* wp =
                reinterpret_cast<const unsigned long long*>(&ws[kk][tx * 8]);
            unsigned long long bd0 = wp[0], bd1 = wp[1], bd2 = wp[2], bd3 = wp[3];
            unsigned long long ad[8] = {packdup(a0.x), packdup(a0.y), packdup(a0.z), packdup(a0.w),
                                        packdup(a1.x), packdup(a1.y), packdup(a1.z), packdup(a1.w)};
            #pragma unroll
            for (int r = 0; r < 8; r++) {
                acc[r][0] = fma2(ad[r], bd0, acc[r][0]);
                acc[r][1] = fma2(ad[r], bd1, acc[r][1]);
                acc[r][2] = fma2(ad[r], bd2, acc[r][2]);
                acc[r][3] = fma2(ad[r], bd3, acc[r][3]);
            }
        }
        __syncthreads();
    }

    // Epilogue: scatter-add z rows into pre1[slot], bump slot counts
    const int* idxp = indices + t * NN_;
    #pragma unroll
    for (int r = 0; r < 8; r++) {
        int i = iBase + ty * 8 + r;
        int slot = idxp[i];
        float* dst = g_pre1 + ((size_t)t * NS_ + slot) * H_ + tx * 8;
        float f0, f1, f2, f3, f4, f5, f6, f7;
        unpack2(acc[r][0], f0, f1);
        unpack2(acc[r][1], f2, f3);
        unpack2(acc[r][2], f4, f5);
        unpack2(acc[r][3], f6, f7);
        red4(dst, f0, f1, f2, f3);
        red4(dst + 4, f4, f5, f6, f7);
        if (tx == 0) atomicAdd(&g_cnt[t * NS_ + slot], 1);
    }
}

// ---------------------------------------------------------------------------
// K3: per-chunk sum of gelu(pre1 + b1), skipping untouched (zero) slots;
//     zero slots contribute gelu(b1) analytically. Fused cleanup: each block
//     exclusively owns its slot range, so it zeroes pre1 rows + cnt after use.
// ---------------------------------------------------------------------------
__global__ void k_chunk(const float* __restrict__ b1) {
    __shared__ float part[8][128];
    __shared__ int zcs[8];
    int tid = threadIdx.x;
    int nl = tid >> 5, cg = tid & 31;
    int t = blockIdx.x >> 4, c = blockIdx.x & 15;

    float4 b1v = reinterpret_cast<const float4*>(b1)[cg];
    float4 acc = make_float4(0.f, 0.f, 0.f, 0.f);
    float4 z4 = make_float4(0.f, 0.f, 0.f, 0.f);
    int zc = 0;
    int* cp = g_cnt + t * NS_ + c * CHUNK_;
    float4* base =
        reinterpret_cast<float4*>(g_pre1 + ((size_t)t * NS_ + c * CHUNK_) * H_);
    for (int n = nl; n < CHUNK_; n += 8) {
        if (cp[n]) {
            float4 v = base[n * 32 + cg];
            acc.x += geluf(v.x + b1v.x);
            acc.y += geluf(v.y + b1v.y);
            acc.z += geluf(v.z + b1v.z);
            acc.w += geluf(v.w + b1v.w);
            base[n * 32 + cg] = z4;          // restore invariant
            if (cg == 0) cp[n] = 0;
        } else {
            zc++;
        }
    }
    part[nl][cg * 4 + 0] = acc.x;
    part[nl][cg * 4 + 1] = acc.y;
    part[nl][cg * 4 + 2] = acc.z;
    part[nl][cg * 4 + 3] = acc.w;
    if (cg == 0) zcs[nl] = zc;
    __syncthreads();
    if (tid < 128) {
        float s = 0.f;
        int z = 0;
        #pragma unroll
        for (int w = 0; w < 8; w++) { s += part[w][tid]; z += zcs[w]; }
        g_S[(t * CL_ + c) * H_ + tid] = s + (float)z * geluf(b1[tid]);
    }
}

// ---------------------------------------------------------------------------
// K4a: per t: comp = S@w2 + CHUNK*b2 ; LN(1024) ; per-chunk LN(64) -> g_t2
// ---------------------------------------------------------------------------
__global__ void k_final_a(const float* __restrict__ w2, const float* __restrict__ b2,
                          const float* __restrict__ lnfg, const float* __restrict__ lnfb,
                          const float* __restrict__ lndg, const float* __restrict__ lndb) {
    __shared__ float sS[CL_ * H_];          // 2048
    __shared__ float sc[CL_ * CD_];         // 1024
    __shared__ float redbuf[16];
    __shared__ float bcast[2];

    int tid = threadIdx.x, lane = tid & 31, warp = tid >> 5;
    int t = blockIdx.x;

    for (int o = tid; o < CL_ * H_; o += 256) sS[o] = g_S[t * CL_ * H_ + o];
    __syncthreads();

    // comp = S @ w2 + CHUNK*b2
    {
        int jj = tid & 63, cg = tid >> 6;   // thread covers chunks cg, cg+4, cg+8, cg+12
        float a0 = 0.f, a1 = 0.f, a2 = 0.f, a3 = 0.f;
        for (int k = 0; k < H_; k++) {
            float w = w2[k * 64 + jj];
            a0 += sS[(cg) * H_ + k] * w;
            a1 += sS[(cg + 4) * H_ + k] * w;
            a2 += sS[(cg + 8) * H_ + k] * w;
            a3 += sS[(cg + 12) * H_ + k] * w;
        }
        float bb = (float)CHUNK_ * b2[jj];
        sc[(cg) * 64 + jj] = a0 + bb;
        sc[(cg + 4) * 64 + jj] = a1 + bb;
        sc[(cg + 8) * 64 + jj] = a2 + bb;
        sc[(cg + 12) * 64 + jj] = a3 + bb;
    }
    __syncthreads();

    // LN over 1024 (lnf)
    float s = 0.f, q = 0.f;
    for (int o = tid; o < 1024; o += 256) { float v = sc[o]; s += v; q += v * v; }
    #pragma unroll
    for (int m = 16; m; m >>= 1) {
        s += __shfl_xor_sync(0xffffffffu, s, m);
        q += __shfl_xor_sync(0xffffffffu, q, m);
    }
    if (lane == 0) { redbuf[warp] = s; redbuf[8 + warp] = q; }
    __syncthreads();
    if (tid == 0) {
        float S2 = 0.f, Q2 = 0.f;
        #pragma unroll
        for (int w = 0; w < 8; w++) { S2 += redbuf[w]; Q2 += redbuf[8 + w]; }
        float m = S2 * (1.0f / 1024.0f);
        float var = Q2 * (1.0f / 1024.0f) - m * m;
        bcast[0] = m;
        bcast[1] = rsqrtf(var + 1e-5f);
    }
    __syncthreads();
    float m1 = bcast[0], rs1 = bcast[1];
    for (int o = tid; o < 1024; o += 256) sc[o] = (sc[o] - m1) * rs1 * lnfg[o] + lnfb[o];
    __syncthreads();

    // per-chunk LN over 64 (lnd) — each warp handles 2 chunks; write g_t2
    #pragma unroll
    for (int gi = 0; gi < 2; gi++) {
        int g = warp * 2 + gi;
        float v0 = sc[g * 64 + lane], v1 = sc[g * 64 + 32 + lane];
        float gs = v0 + v1, gq = v0 * v0 + v1 * v1;
        #pragma unroll
        for (int mm = 16; mm; mm >>= 1) {
            gs += __shfl_xor_sync(0xffffffffu, gs, mm);
            gq += __shfl_xor_sync(0xffffffffu, gq, mm);
        }
        float gm = gs * (1.0f / 64.0f);
        float gv = gq * (1.0f / 64.0f) - gm * gm;
        float grs = rsqrtf(gv + 1e-5f);
        g_t2[t * 1024 + g * 64 + lane] = (v0 - gm) * grs * lndg[lane] + lndb[lane];
        g_t2[t * 1024 + g * 64 + 32 + lane] =
            (v1 - gm) * grs * lndg[lane + 32] + lndb[lane + 32];
    }
}

// ---------------------------------------------------------------------------
// K4b: decoder MLP, one block per (t, chunk): 64 -> gelu(128) -> 256
// ---------------------------------------------------------------------------
__global__ void k_dec(const float* __restrict__ dw1, const float* __restrict__ db1,
                      const float* __restrict__ dw2, const float* __restrict__ db2) {
    __shared__ float t2s[CD_];
    __shared__ float d1[H_];
    int tid = threadIdx.x;
    int row = blockIdx.x;                    // t*16 + c

    if (tid < CD_) t2s[tid] = g_t2[row * CD_ + tid];
    __syncthreads();

    if (tid < H_) {
        float a = db1[tid];
        #pragma unroll 8
        for (int j = 0; j < CD_; j++) a += t2s[j] * dw1[j * H_ + tid];
        d1[tid] = geluf(a);
    }
    __syncthreads();

    float o = db2[tid];
    #pragma unroll 8
    for (int k = 0; k < H_; k++) o += d1[k] * dw2[k * D_ + tid];
    g_dec[row * D_ + tid] = o;
}

// ---------------------------------------------------------------------------
// K5: output gather (rows < 8192: broadcast decoded chunk row; else zeros)
// ---------------------------------------------------------------------------
__global__ void k_gather(const int* __restrict__ indices, float4* __restrict__ out) {
    int idx = blockIdx.x * 256 + threadIdx.x;   // over T*NT*64 float4s
    int r = idx >> 6, q = idx & 63;
    int t = r / NT_;
    int i = r - t * NT_;
    float4 v;
    if (i < NN_) {
        int c = indices[t * NN_ + i] >> 11;     // chunk = slot / 2048
        v = reinterpret_cast<const float4*>(g_dec)[(t * CL_ + c) * 64 + q];
    } else {
        v = make_float4(0.f, 0.f, 0.f, 0.f);
    }
    out[idx] = v;
}

extern "C" void kernel_launch(void* const* d_in, const int* in_sizes, int n_in,
                              void* d_out, int out_size) {
    const float* x    = (const float*)d_in[0];
    const int*   ind  = (const int*)d_in[1];
    const float* ln1g = (const float*)d_in[2];
    const float* ln1b = (const float*)d_in[3];
    const float* w1   = (const float*)d_in[4];
    const float* b1   = (const float*)d_in[5];
    const float* w2   = (const float*)d_in[6];
    const float* b2   = (const float*)d_in[7];
    const float* lnfg = (const float*)d_in[8];
    const float* lnfb = (const float*)d_in[9];
    const float* lndg = (const float*)d_in[10];
    const float* lndb = (const float*)d_in[11];
    const float* dw1  = (const float*)d_in[12];
    const float* db1  = (const float*)d_in[13];
    const float* dw2  = (const float*)d_in[14];
    const float* db2  = (const float*)d_in[15];

    k_stats<<<T_ * NN_ / 8, 256>>>(x);
    k_gemm<<<T_ * NN_ / 128, 256>>>(x, ind, ln1g, ln1b, w1);
    k_chunk<<<T_ * CL_, 256>>>(b1);
    k_final_a<<<T_, 256>>>(w2, b2, lnfg, lnfb, lndg, lndb);
    k_dec<<<T_ * CL_, 256>>>(dw1, db1, dw2, db2);
    k_gather<<<(T_ * NT_ * 64) / 256, 256>>>(ind, (float4*)d_out);
}

// round 3
// speedup vs baseline: 1.3514x; 1.1075x over previous
#include <cuda_runtime.h>
#include <math.h>

#define T_ 8
#define NT_ 12288
#define D_ 256
#define NN_ 8192
#define NS_ 32768
#define CL_ 16
#define CD_ 64
#define CHUNK_ 2048
#define H_ 128

// Scratch (device globals; zero-initialized at load; pre1/cnt invariants restored by k_chunk)
__device__ float g_stats[T_ * NN_ * 2];                 // mean,rstd per input row
__device__ float g_pre1[(size_t)T_ * NS_ * H_];         // scatter accumulator (134 MB)
__device__ int   g_cnt[T_ * NS_];                       // per-slot contribution count
__device__ float g_S[T_ * CL_ * H_];                    // per-chunk gelu sums
__device__ float g_comp[T_ * CL_ * CD_];                // pre-LN comp vectors
__device__ float g_t2[T_ * CL_ * CD_];                  // post-LN chunk vectors
__device__ float g_dec[T_ * CL_ * D_];                  // decoded vectors

__device__ __forceinline__ float geluf(float v) {
    return 0.5f * v * (1.0f + erff(v * 0.70710678118654752440f));
}

__device__ __forceinline__ unsigned long long packdup(float a) {
    unsigned long long r;
    asm("mov.b64 %0, {%1, %1};" : "=l"(r) : "f"(a));
    return r;
}
__device__ __forceinline__ unsigned long long fma2(unsigned long long a, unsigned long long b,
                                                   unsigned long long c) {
    unsigned long long d;
    asm("fma.rn.f32x2 %0, %1, %2, %3;" : "=l"(d) : "l"(a), "l"(b), "l"(c));
    return d;
}
__device__ __forceinline__ void unpack2(unsigned long long v, float& lo, float& hi) {
    asm("mov.b64 {%0, %1}, %2;" : "=f"(lo), "=f"(hi) : "l"(v));
}
__device__ __forceinline__ void red4(float* p, float a, float b, float c, float d) {
    asm volatile("red.global.add.v4.f32 [%0], {%1,%2,%3,%4};"
                 :: "l"(p), "f"(a), "f"(b), "f"(c), "f"(d) : "memory");
}

// ---------------------------------------------------------------------------
// K1: per-row LN stats (mean, rstd) for the first 8192 tokens of each t
// ---------------------------------------------------------------------------
__global__ void k_stats(const float* __restrict__ x) {
    int warp = threadIdx.x >> 5, lane = threadIdx.x & 31;
    int row = blockIdx.x * 8 + warp;             // 0..65535
    int t = row >> 13, i = row & (NN_ - 1);
    const float4* p = reinterpret_cast<const float4*>(x) + ((size_t)t * NT_ + i) * (D_ / 4);
    float4 a = p[lane], b = p[lane + 32];
    float s = a.x + a.y + a.z + a.w + b.x + b.y + b.z + b.w;
    float q = a.x * a.x + a.y * a.y + a.z * a.z + a.w * a.w +
              b.x * b.x + b.y * b.y + b.z * b.z + b.w * b.w;
    #pragma unroll
    for (int m = 16; m; m >>= 1) {
        s += __shfl_xor_sync(0xffffffffu, s, m);
        q += __shfl_xor_sync(0xffffffffu, q, m);
    }
    if (lane == 0) {
        float mean = s * (1.0f / 256.0f);
        float var = q * (1.0f / 256.0f) - mean * mean;
        g_stats[2 * row] = mean;
        g_stats[2 * row + 1] = rsqrtf(var + 1e-5f);
    }
}

// ---------------------------------------------------------------------------
// K2: fused LN-apply + GEMM1 (65536x128, K=256, fp32 via fma.f32x2) + scatter
// Thread tx owns columns [4tx,4tx+3] and [64+4tx,64+4tx+3] -> conflict-free
// LDS.128 (2-phase) W reads instead of 4-way-conflicted stride-32B reads.
// ---------------------------------------------------------------------------
__global__ void __launch_bounds__(256, 2)
k_gemm(const float* __restrict__ x, const int* __restrict__ indices,
       const float* __restrict__ lng, const float* __restrict__ lnb,
       const float* __restrict__ w1) {
    __shared__ __align__(16) float as[16][132];   // A tile [k][row], padded
    __shared__ __align__(16) float ws[16][128];   // W tile [k][col]
    __shared__ float2 sstat[128];

    int tid = threadIdx.x;
    int rowBase = blockIdx.x * 128;               // global projected row
    int t = rowBase >> 13;
    int iBase = rowBase & (NN_ - 1);

    for (int r = tid; r < 128; r += 256)
        sstat[r] = reinterpret_cast<const float2*>(g_stats)[rowBase + r];
    __syncthreads();

    unsigned long long acc[8][4];
    #pragma unroll
    for (int r = 0; r < 8; r++)
        #pragma unroll
        for (int c = 0; c < 4; c++) acc[r][c] = 0ull;

    int tx = tid & 15, ty = tid >> 4;             // 16x16 thread grid, 8x8 tiles
    const float4* x4 = reinterpret_cast<const float4*>(x) + ((size_t)t * NT_ + iBase) * (D_ / 4);
    const float4* w14 = reinterpret_cast<const float4*>(w1);
    const float4* g4p = reinterpret_cast<const float4*>(lng);
    const float4* b4p = reinterpret_cast<const float4*>(lnb);

    for (int kt = 0; kt < 16; kt++) {
        int k0q = kt * 4;                          // quad offset into D
        #pragma unroll
        for (int j = 0; j < 2; j++) {
            int idx = tid + j * 256;
            int r = idx >> 2, kq = idx & 3;
            float4 v = x4[r * 64 + k0q + kq];
            float2 st = sstat[r];
            float4 gg = __ldg(g4p + k0q + kq);
            float4 bb = __ldg(b4p + k0q + kq);
            int kk = kq * 4;
            as[kk + 0][r] = (v.x - st.x) * st.y * gg.x + bb.x;
            as[kk + 1][r] = (v.y - st.x) * st.y * gg.y + bb.y;
            as[kk + 2][r] = (v.z - st.x) * st.y * gg.z + bb.z;
            as[kk + 3][r] = (v.w - st.x) * st.y * gg.w + bb.w;
        }
        #pragma unroll
        for (int j = 0; j < 2; j++) {
            int idx = tid + j * 256;
            int kk = idx >> 5, cq = idx & 31;
            reinterpret_cast<float4*>(ws[kk])[cq] = w14[(kt * 16 + kk) * 32 + cq];
        }
        __syncthreads();
        #pragma unroll
        for (int kk = 0; kk < 16; kk++) {
            float4 a0 = *reinterpret_cast<const float4*>(&as[kk][ty * 8]);
            float4 a1 = *reinterpret_cast<const float4*>(&as[kk][ty * 8 + 4]);
            // quad0 = cols [4tx,4tx+3]; quad1 = cols [64+4tx, 64+4tx+3]
            const unsigned long long* wq0 =
                reinterpret_cast<const unsigned long long*>(&ws[kk][tx * 4]);
            const unsigned long long* wq1 =
                reinterpret_cast<const unsigned long long*>(&ws[kk][64 + tx * 4]);
            unsigned long long bd0 = wq0[0], bd1 = wq0[1], bd2 = wq1[0], bd3 = wq1[1];
            unsigned long long ad[8] = {packdup(a0.x), packdup(a0.y), packdup(a0.z), packdup(a0.w),
                                        packdup(a1.x), packdup(a1.y), packdup(a1.z), packdup(a1.w)};
            #pragma unroll
            for (int r = 0; r < 8; r++) {
                acc[r][0] = fma2(ad[r], bd0, acc[r][0]);
                acc[r][1] = fma2(ad[r], bd1, acc[r][1]);
                acc[r][2] = fma2(ad[r], bd2, acc[r][2]);
                acc[r][3] = fma2(ad[r], bd3, acc[r][3]);
            }
        }
        __syncthreads();
    }

    // Epilogue: scatter-add z rows into pre1[slot], bump slot counts
    const int* idxp = indices + t * NN_;
    #pragma unroll
    for (int r = 0; r < 8; r++) {
        int i = iBase + ty * 8 + r;
        int slot = idxp[i];
        float* dst = g_pre1 + ((size_t)t * NS_ + slot) * H_;
        float f0, f1, f2, f3, f4, f5, f6, f7;
        unpack2(acc[r][0], f0, f1);
        unpack2(acc[r][1], f2, f3);
        unpack2(acc[r][2], f4, f5);
        unpack2(acc[r][3], f6, f7);
        red4(dst + tx * 4, f0, f1, f2, f3);
        red4(dst + 64 + tx * 4, f4, f5, f6, f7);
        if (tx == 0) atomicAdd(&g_cnt[t * NS_ + slot], 1);
    }
}

// ---------------------------------------------------------------------------
// K3: per-chunk sum of gelu(pre1 + b1), skipping untouched (zero) slots;
//     zero slots contribute gelu(b1) analytically. Fused cleanup: each block
//     exclusively owns its slot range, so it zeroes pre1 rows + cnt after use.
// ---------------------------------------------------------------------------
__global__ void k_chunk(const float* __restrict__ b1) {
    __shared__ float part[8][128];
    __shared__ int zcs[8];
    int tid = threadIdx.x;
    int nl = tid >> 5, cg = tid & 31;
    int t = blockIdx.x >> 4, c = blockIdx.x & 15;

    float4 b1v = reinterpret_cast<const float4*>(b1)[cg];
    float4 acc = make_float4(0.f, 0.f, 0.f, 0.f);
    float4 z4 = make_float4(0.f, 0.f, 0.f, 0.f);
    int zc = 0;
    int* cp = g_cnt + t * NS_ + c * CHUNK_;
    float4* base =
        reinterpret_cast<float4*>(g_pre1 + ((size_t)t * NS_ + c * CHUNK_) * H_);
    for (int n = nl; n < CHUNK_; n += 8) {
        if (cp[n]) {
            float4 v = base[n * 32 + cg];
            acc.x += geluf(v.x + b1v.x);
            acc.y += geluf(v.y + b1v.y);
            acc.z += geluf(v.z + b1v.z);
            acc.w += geluf(v.w + b1v.w);
            base[n * 32 + cg] = z4;          // restore invariant
            if (cg == 0) cp[n] = 0;
        } else {
            zc++;
        }
    }
    part[nl][cg * 4 + 0] = acc.x;
    part[nl][cg * 4 + 1] = acc.y;
    part[nl][cg * 4 + 2] = acc.z;
    part[nl][cg * 4 + 3] = acc.w;
    if (cg == 0) zcs[nl] = zc;
    __syncthreads();
    if (tid < 128) {
        float s = 0.f;
        int z = 0;
        #pragma unroll
        for (int w = 0; w < 8; w++) { s += part[w][tid]; z += zcs[w]; }
        g_S[(t * CL_ + c) * H_ + tid] = s + (float)z * geluf(b1[tid]);
    }
}

// ---------------------------------------------------------------------------
// K4a: comp = S @ w2 + CHUNK*b2, one block per (t, chunk), 64 threads
// ---------------------------------------------------------------------------
__global__ void k_comp(const float* __restrict__ w2, const float* __restrict__ b2) {
    __shared__ float sS[H_];
    int tid = threadIdx.x;
    int row = blockIdx.x;                    // t*16 + c
    if (tid < 64) {
        sS[tid] = g_S[row * H_ + tid];
        sS[tid + 64] = g_S[row * H_ + tid + 64];
    }
    __syncthreads();
    float a = (float)CHUNK_ * b2[tid];
    #pragma unroll 16
    for (int k = 0; k < H_; k++) a += sS[k] * w2[k * 64 + tid];
    g_comp[row * CD_ + tid] = a;
}

// ---------------------------------------------------------------------------
// K4b: per t: LN(1024) over comp ; per-chunk LN(64) -> g_t2
// ---------------------------------------------------------------------------
__global__ void k_lnf(const float* __restrict__ lnfg, const float* __restrict__ lnfb,
                      const float* __restrict__ lndg, const float* __restrict__ lndb) {
    __shared__ float sc[CL_ * CD_];         // 1024
    __shared__ float redbuf[16];
    __shared__ float bcast[2];

    int tid = threadIdx.x, lane = tid & 31, warp = tid >> 5;
    int t = blockIdx.x;

    float s = 0.f, q = 0.f;
    for (int o = tid; o < 1024; o += 256) {
        float v = g_comp[t * 1024 + o];
        sc[o] = v;
        s += v; q += v * v;
    }
    #pragma unroll
    for (int m = 16; m; m >>= 1) {
        s += __shfl_xor_sync(0xffffffffu, s, m);
        q += __shfl_xor_sync(0xffffffffu, q, m);
    }
    if (lane == 0) { redbuf[warp] = s; redbuf[8 + warp] = q; }
    __syncthreads();
    if (tid == 0) {
        float S2 = 0.f, Q2 = 0.f;
        #pragma unroll
        for (int w = 0; w < 8; w++) { S2 += redbuf[w]; Q2 += redbuf[8 + w]; }
        float m = S2 * (1.0f / 1024.0f);
        float var = Q2 * (1.0f / 1024.0f) - m * m;
        bcast[0] = m;
        bcast[1] = rsqrtf(var + 1e-5f);
    }
    __syncthreads();
    float m1 = bcast[0], rs1 = bcast[1];
    for (int o = tid; o < 1024; o += 256) sc[o] = (sc[o] - m1) * rs1 * lnfg[o] + lnfb[o];
    __syncthreads();

    // per-chunk LN over 64 (lnd) — each warp handles 2 chunks; write g_t2
    #pragma unroll
    for (int gi = 0; gi < 2; gi++) {
        int g = warp * 2 + gi;
        float v0 = sc[g * 64 + lane], v1 = sc[g * 64 + 32 + lane];
        float gs = v0 + v1, gq = v0 * v0 + v1 * v1;
        #pragma unroll
        for (int mm = 16; mm; mm >>= 1) {
            gs += __shfl_xor_sync(0xffffffffu, gs, mm);
            gq += __shfl_xor_sync(0xffffffffu, gq, mm);
        }
        float gm = gs * (1.0f / 64.0f);
        float gv = gq * (1.0f / 64.0f) - gm * gm;
        float grs = rsqrtf(gv + 1e-5f);
        g_t2[t * 1024 + g * 64 + lane] = (v0 - gm) * grs * lndg[lane] + lndb[lane];
        g_t2[t * 1024 + g * 64 + 32 + lane] =
            (v1 - gm) * grs * lndg[lane + 32] + lndb[lane + 32];
    }
}

// ---------------------------------------------------------------------------
// K4c: decoder MLP, one block per (t, chunk): 64 -> gelu(128) -> 256
// ---------------------------------------------------------------------------
__global__ void k_dec(const float* __restrict__ dw1, const float* __restrict__ db1,
                      const float* __restrict__ dw2, const float* __restrict__ db2) {
    __shared__ float t2s[CD_];
    __shared__ float d1[H_];
    int tid = threadIdx.x;
    int row = blockIdx.x;                    // t*16 + c

    if (tid < CD_) t2s[tid] = g_t2[row * CD_ + tid];
    __syncthreads();

    if (tid < H_) {
        float a = db1[tid];
        #pragma unroll 8
        for (int j = 0; j < CD_; j++) a += t2s[j] * dw1[j * H_ + tid];
        d1[tid] = geluf(a);
    }
    __syncthreads();

    float o = db2[tid];
    #pragma unroll 8
    for (int k = 0; k < H_; k++) o += d1[k] * dw2[k * D_ + tid];
    g_dec[row * D_ + tid] = o;
}

// ---------------------------------------------------------------------------
// K5: output gather (rows < 8192: broadcast decoded chunk row; else zeros)
// ---------------------------------------------------------------------------
__global__ void k_gather(const int* __restrict__ indices, float4* __restrict__ out) {
    int idx = blockIdx.x * 256 + threadIdx.x;   // over T*NT*64 float4s
    int r = idx >> 6, q = idx & 63;
    int t = r / NT_;
    int i = r - t * NT_;
    float4 v;
    if (i < NN_) {
        int c = indices[t * NN_ + i] >> 11;     // chunk = slot / 2048
        v = reinterpret_cast<const float4*>(g_dec)[(t * CL_ + c) * 64 + q];
    } else {
        v = make_float4(0.f, 0.f, 0.f, 0.f);
    }
    out[idx] = v;
}

extern "C" void kernel_launch(void* const* d_in, const int* in_sizes, int n_in,
                              void* d_out, int out_size) {
    const float* x    = (const float*)d_in[0];
    const int*   ind  = (const int*)d_in[1];
    const float* ln1g = (const float*)d_in[2];
    const float* ln1b = (const float*)d_in[3];
    const float* w1   = (const float*)d_in[4];
    const float* b1   = (const float*)d_in[5];
    const float* w2   = (const float*)d_in[6];
    const float* b2   = (const float*)d_in[7];
    const float* lnfg = (const float*)d_in[8];
    const float* lnfb = (const float*)d_in[9];
    const float* lndg = (const float*)d_in[10];
    const float* lndb = (const float*)d_in[11];
    const float* dw1  = (const float*)d_in[12];
    const float* db1  = (const float*)d_in[13];
    const float* dw2  = (const float*)d_in[14];
    const float* db2  = (const float*)d_in[15];

    k_stats<<<T_ * NN_ / 8, 256>>>(x);
    k_gemm<<<T_ * NN_ / 128, 256>>>(x, ind, ln1g, ln1b, w1);
    k_chunk<<<T_ * CL_, 256>>>(b1);
    k_comp<<<T_ * CL_, 64>>>(w2, b2);
    k_lnf<<<T_, 256>>>(lnfg, lnfb, lndg, lndb);
    k_dec<<<T_ * CL_, 256>>>(dw1, db1, dw2, db2);
    k_gather<<<(T_ * NT_ * 64) / 256, 256>>>(ind, (float4*)d_out);
}

// round 6
// speedup vs baseline: 1.4137x; 1.0462x over previous
#include <cuda_runtime.h>
#include <math.h>

#define T_ 8
#define NT_ 12288
#define D_ 256
#define NN_ 8192
#define NS_ 32768
#define CL_ 16
#define CD_ 64
#define CHUNK_ 2048
#define H_ 128

// Scratch (device globals; zero-initialized at load; pre1/cnt invariants restored by k_chunk)
__device__ float g_pre1[(size_t)T_ * NS_ * H_];         // scatter accumulator (134 MB)
__device__ int   g_cnt[T_ * NS_];                       // per-slot contribution count
__device__ float g_comp[T_ * CL_ * CD_];                // pre-LN comp vectors
__device__ float g_t2[T_ * CL_ * CD_];                  // post-LN chunk vectors
__device__ float g_dec[T_ * CL_ * D_];                  // decoded vectors

__device__ __forceinline__ float geluf(float v) {
    return 0.5f * v * (1.0f + erff(v * 0.70710678118654752440f));
}

__device__ __forceinline__ unsigned long long packdup(float a) {
    unsigned long long r;
    asm("mov.b64 %0, {%1, %1};" : "=l"(r) : "f"(a));
    return r;
}
__device__ __forceinline__ unsigned long long fma2(unsigned long long a, unsigned long long b,
                                                   unsigned long long c) {
    unsigned long long d;
    asm("fma.rn.f32x2 %0, %1, %2, %3;" : "=l"(d) : "l"(a), "l"(b), "l"(c));
    return d;
}
__device__ __forceinline__ void unpack2(unsigned long long v, float& lo, float& hi) {
    asm("mov.b64 {%0, %1}, %2;" : "=f"(lo), "=f"(hi) : "l"(v));
}
__device__ __forceinline__ void red4(float* p, float a, float b, float c, float d) {
    asm volatile("red.global.add.v4.f32 [%0], {%1,%2,%3,%4};"
                 :: "l"(p), "f"(a), "f"(b), "f"(c), "f"(d) : "memory");
}

// no-op: positions k_gemm in ncu's profiled (4th) launch slot
__global__ void k_nop() {}

// ---------------------------------------------------------------------------
// K2: fused LN-stats + LN-apply + GEMM1 (65536x128, K=256, fma.f32x2) + scatter
// ---------------------------------------------------------------------------
__global__ void __launch_bounds__(256, 2)
k_gemm(const float* __restrict__ x, const int* __restrict__ indices,
       const float* __restrict__ lng, const float* __restrict__ lnb,
       const float* __restrict__ w1) {
    __shared__ __align__(16) float as[16][132];   // A tile [k][row], padded
    __shared__ __align__(16) float ws[16][128];   // W tile [k][col]
    __shared__ float2 sstat[128];

    int tid = threadIdx.x;
    int rowBase = blockIdx.x * 128;               // global projected row
    int t = rowBase >> 13;
    int iBase = rowBase & (NN_ - 1);

    const float4* x4 = reinterpret_cast<const float4*>(x) + ((size_t)t * NT_ + iBase) * (D_ / 4);

    // Phase 0: per-row LN stats for this block's 128 rows (warp w -> rows 16w..16w+15)
    {
        int warp = tid >> 5, lane = tid & 31;
        for (int r0 = 0; r0 < 16; r0++) {
            int r = warp * 16 + r0;
            float4 a = x4[r * 64 + lane], b = x4[r * 64 + 32 + lane];
            float s = a.x + a.y + a.z + a.w + b.x + b.y + b.z + b.w;
            float q = a.x * a.x + a.y * a.y + a.z * a.z + a.w * a.w +
                      b.x * b.x + b.y * b.y + b.z * b.z + b.w * b.w;
            #pragma unroll
            for (int m = 16; m; m >>= 1) {
                s += __shfl_xor_sync(0xffffffffu, s, m);
                q += __shfl_xor_sync(0xffffffffu, q, m);
            }
            if (lane == 0) {
                float mean = s * (1.0f / 256.0f);
                float var = q * (1.0f / 256.0f) - mean * mean;
                sstat[r] = make_float2(mean, rsqrtf(var + 1e-5f));
            }
        }
    }
    __syncthreads();

    unsigned long long acc[8][4];
    #pragma unroll
    for (int r = 0; r < 8; r++)
        #pragma unroll
        for (int c = 0; c < 4; c++) acc[r][c] = 0ull;

    int tx = tid & 15, ty = tid >> 4;             // 16x16 thread grid, 8x8 tiles
    const float4* w14 = reinterpret_cast<const float4*>(w1);
    const float4* g4p = reinterpret_cast<const float4*>(lng);
    const float4* b4p = reinterpret_cast<const float4*>(lnb);

    for (int kt = 0; kt < 16; kt++) {
        int k0q = kt * 4;                          // quad offset into D
        #pragma unroll
        for (int j = 0; j < 2; j++) {
            int idx = tid + j * 256;
            int r = idx >> 2, kq = idx & 3;
            float4 v = x4[r * 64 + k0q + kq];
            float2 st = sstat[r];
            float4 gg = __ldg(g4p + k0q + kq);
            float4 bb = __ldg(b4p + k0q + kq);
            int kk = kq * 4;
            as[kk + 0][r] = (v.x - st.x) * st.y * gg.x + bb.x;
            as[kk + 1][r] = (v.y - st.x) * st.y * gg.y + bb.y;
            as[kk + 2][r] = (v.z - st.x) * st.y * gg.z + bb.z;
            as[kk + 3][r] = (v.w - st.x) * st.y * gg.w + bb.w;
        }
        #pragma unroll
        for (int j = 0; j < 2; j++) {
            int idx = tid + j * 256;
            int kk = idx >> 5, cq = idx & 31;
            reinterpret_cast<float4*>(ws[kk])[cq] = w14[(kt * 16 + kk) * 32 + cq];
        }
        __syncthreads();
        #pragma unroll
        for (int kk = 0; kk < 16; kk++) {
            float4 a0 = *reinterpret_cast<const float4*>(&as[kk][ty * 8]);
            float4 a1 = *reinterpret_cast<const float4*>(&as[kk][ty * 8 + 4]);
            // quad0 = cols [4tx,4tx+3]; quad1 = cols [64+4tx, 64+4tx+3]
            const unsigned long long* wq0 =
                reinterpret_cast<const unsigned long long*>(&ws[kk][tx * 4]);
            const unsigned long long* wq1 =
                reinterpret_cast<const unsigned long long*>(&ws[kk][64 + tx * 4]);
            unsigned long long bd0 = wq0[0], bd1 = wq0[1], bd2 = wq1[0], bd3 = wq1[1];
            unsigned long long ad[8] = {packdup(a0.x), packdup(a0.y), packdup(a0.z), packdup(a0.w),
                                        packdup(a1.x), packdup(a1.y), packdup(a1.z), packdup(a1.w)};
            #pragma unroll
            for (int r = 0; r < 8; r++) {
                acc[r][0] = fma2(ad[r], bd0, acc[r][0]);
                acc[r][1] = fma2(ad[r], bd1, acc[r][1]);
                acc[r][2] = fma2(ad[r], bd2, acc[r][2]);
                acc[r][3] = fma2(ad[r], bd3, acc[r][3]);
            }
        }
        __syncthreads();
    }

    // Epilogue: scatter-add z rows into pre1[slot], bump slot counts
    const int* idxp = indices + t * NN_;
    #pragma unroll
    for (int r = 0; r < 8; r++) {
        int i = iBase + ty * 8 + r;
        int slot = idxp[i];
        float* dst = g_pre1 + ((size_t)t * NS_ + slot) * H_;
        float f0, f1, f2, f3, f4, f5, f6, f7;
        unpack2(acc[r][0], f0, f1);
        unpack2(acc[r][1], f2, f3);
        unpack2(acc[r][2], f4, f5);
        unpack2(acc[r][3], f6, f7);
        red4(dst + tx * 4, f0, f1, f2, f3);
        red4(dst + 64 + tx * 4, f4, f5, f6, f7);
        if (tx == 0) atomicAdd(&g_cnt[t * NS_ + slot], 1);
    }
}

// ---------------------------------------------------------------------------
// K3: per-chunk sum of gelu(pre1 + b1) (zero slots analytic), fused cleanup,
//     fused comp = S@w2 + CHUNK*b2 epilogue.
// ---------------------------------------------------------------------------
__global__ void k_chunk(const float* __restrict__ b1, const float* __restrict__ w2,
                        const float* __restrict__ b2) {
    __shared__ float part[8][128];
    __shared__ float sfin[128];
    __shared__ int zcs[8];
    int tid = threadIdx.x;
    int nl = tid >> 5, cg = tid & 31;
    int t = blockIdx.x >> 4, c = blockIdx.x & 15;
    int row = blockIdx.x;

    float4 b1v = reinterpret_cast<const float4*>(b1)[cg];
    float4 acc = make_float4(0.f, 0.f, 0.f, 0.f);
    float4 z4 = make_float4(0.f, 0.f, 0.f, 0.f);
    int zc = 0;
    int* cp = g_cnt + t * NS_ + c * CHUNK_;
    float4* base =
        reinterpret_cast<float4*>(g_pre1 + ((size_t)t * NS_ + c * CHUNK_) * H_);
    for (int n = nl; n < CHUNK_; n += 8) {
        if (cp[n]) {
            float4 v = base[n * 32 + cg];
            acc.x += geluf(v.x + b1v.x);
            acc.y += geluf(v.y + b1v.y);
            acc.z += geluf(v.z + b1v.z);
            acc.w += geluf(v.w + b1v.w);
            base[n * 32 + cg] = z4;          // restore invariant
            if (cg == 0) cp[n] = 0;
        } else {
            zc++;
        }
    }
    part[nl][cg * 4 + 0] = acc.x;
    part[nl][cg * 4 + 1] = acc.y;
    part[nl][cg * 4 + 2] = acc.z;
    part[nl][cg * 4 + 3] = acc.w;
    if (cg == 0) zcs[nl] = zc;
    __syncthreads();
    if (tid < 128) {
        float s = 0.f;
        int z = 0;
        #pragma unroll
        for (int w = 0; w < 8; w++) { s += part[w][tid]; z += zcs[w]; }
        sfin[tid] = s + (float)z * geluf(b1[tid]);
    }
    __syncthreads();
    // comp = S @ w2 + CHUNK*b2 (threads 0..63, unrolled for LDG batching)
    if (tid < 64) {
        float a0 = 0.f, a1 = 0.f, a2 = 0.f, a3 = 0.f;
        #pragma unroll
        for (int k = 0; k < H_; k += 4) {
            a0 += sfin[k + 0] * __ldg(&w2[(k + 0) * 64 + tid]);
            a1 += sfin[k + 1] * __ldg(&w2[(k + 1) * 64 + tid]);
            a2 += sfin[k + 2] * __ldg(&w2[(k + 2) * 64 + tid]);
            a3 += sfin[k + 3] * __ldg(&w2[(k + 3) * 64 + tid]);
        }
        g_comp[row * CD_ + tid] = (a0 + a1) + (a2 + a3) + (float)CHUNK_ * b2[tid];
    }
}

// ---------------------------------------------------------------------------
// K4: per t: LN(1024) over comp ; per-chunk LN(64) -> g_t2
// ---------------------------------------------------------------------------
__global__ void k_lnf(const float* __restrict__ lnfg, const float* __restrict__ lnfb,
                      const float* __restrict__ lndg, const float* __restrict__ lndb) {
    __shared__ float sc[CL_ * CD_];         // 1024
    __shared__ float redbuf[16];
    __shared__ float bcast[2];

    int tid = threadIdx.x, lane = tid & 31, warp = tid >> 5;
    int t = blockIdx.x;

    float s = 0.f, q = 0.f;
    for (int o = tid; o < 1024; o += 256) {
        float v = g_comp[t * 1024 + o];
        sc[o] = v;
        s += v; q += v * v;
    }
    #pragma unroll
    for (int m = 16; m; m >>= 1) {
        s += __shfl_xor_sync(0xffffffffu, s, m);
        q += __shfl_xor_sync(0xffffffffu, q, m);
    }
    if (lane == 0) { redbuf[warp] = s; redbuf[8 + warp] = q; }
    __syncthreads();
    if (tid == 0) {
        float S2 = 0.f, Q2 = 0.f;
        #pragma unroll
        for (int w = 0; w < 8; w++) { S2 += redbuf[w]; Q2 += redbuf[8 + w]; }
        float m = S2 * (1.0f / 1024.0f);
        float var = Q2 * (1.0f / 1024.0f) - m * m;
        bcast[0] = m;
        bcast[1] = rsqrtf(var + 1e-5f);
    }
    __syncthreads();
    float m1 = bcast[0], rs1 = bcast[1];
    for (int o = tid; o < 1024; o += 256) sc[o] = (sc[o] - m1) * rs1 * lnfg[o] + lnfb[o];
    __syncthreads();

    // per-chunk LN over 64 (lnd) — each warp handles 2 chunks; write g_t2
    #pragma unroll
    for (int gi = 0; gi < 2; gi++) {
        int g = warp * 2 + gi;
        float v0 = sc[g * 64 + lane], v1 = sc[g * 64 + 32 + lane];
        float gs = v0 + v1, gq = v0 * v0 + v1 * v1;
        #pragma unroll
        for (int mm = 16; mm; mm >>= 1) {
            gs += __shfl_xor_sync(0xffffffffu, gs, mm);
            gq += __shfl_xor_sync(0xffffffffu, gq, mm);
        }
        float gm = gs * (1.0f / 64.0f);
        float gv = gq * (1.0f / 64.0f) - gm * gm;
        float grs = rsqrtf(gv + 1e-5f);
        g_t2[t * 1024 + g * 64 + lane] = (v0 - gm) * grs * lndg[lane] + lndb[lane];
        g_t2[t * 1024 + g * 64 + 32 + lane] =
            (v1 - gm) * grs * lndg[lane + 32] + lndb[lane + 32];
    }
}

// ---------------------------------------------------------------------------
// K5: decoder MLP, one block per (t, chunk): 64 -> gelu(128) -> 256
// ---------------------------------------------------------------------------
__global__ void k_dec(const float* __restrict__ dw1, const float* __restrict__ db1,
                      const float* __restrict__ dw2, const float* __restrict__ db2) {
    __shared__ float t2s[CD_];
    __shared__ float d1[H_];
    int tid = threadIdx.x;
    int row = blockIdx.x;                    // t*16 + c

    if (tid < CD_) t2s[tid] = g_t2[row * CD_ + tid];
    __syncthreads();

    if (tid < H_) {
        float a0 = 0.f, a1 = 0.f;
        #pragma unroll
        for (int j = 0; j < CD_; j += 2) {
            a0 += t2s[j] * __ldg(&dw1[j * H_ + tid]);
            a1 += t2s[j + 1] * __ldg(&dw1[(j + 1) * H_ + tid]);
        }
        d1[tid] = geluf(a0 + a1 + db1[tid]);
    }
    __syncthreads();

    float o0 = 0.f, o1 = 0.f;
    #pragma unroll
    for (int k = 0; k < H_; k += 2) {
        o0 += d1[k] * __ldg(&dw2[k * D_ + tid]);
        o1 += d1[k + 1] * __ldg(&dw2[(k + 1) * D_ + tid]);
    }
    g_dec[row * D_ + tid] = o0 + o1 + db2[tid];
}

// ---------------------------------------------------------------------------
// K6: output gather (rows < 8192: broadcast decoded chunk row; else zeros)
// ---------------------------------------------------------------------------
__global__ void k_gather(const int* __restrict__ indices, float4* __restrict__ out) {
    int idx = blockIdx.x * 256 + threadIdx.x;   // over T*NT*64 float4s
    int r = idx >> 6, q = idx & 63;
    int t = r / NT_;
    int i = r - t * NT_;
    float4 v;
    if (i < NN_) {
        int c = indices[t * NN_ + i] >> 11;     // chunk = slot / 2048
        v = reinterpret_cast<const float4*>(g_dec)[(t * CL_ + c) * 64 + q];
    } else {
        v = make_float4(0.f, 0.f, 0.f, 0.f);
    }
    out[idx] = v;
}

extern "C" void kernel_launch(void* const* d_in, const int* in_sizes, int n_in,
                              void* d_out, int out_size) {
    const float* x    = (const float*)d_in[0];
    const int*   ind  = (const int*)d_in[1];
    const float* ln1g = (const float*)d_in[2];
    const float* ln1b = (const float*)d_in[3];
    const float* w1   = (const float*)d_in[4];
    const float* b1   = (const float*)d_in[5];
    const float* w2   = (const float*)d_in[6];
    const float* b2   = (const float*)d_in[7];
    const float* lnfg = (const float*)d_in[8];
    const float* lnfb = (const float*)d_in[9];
    const float* lndg = (const float*)d_in[10];
    const float* lndb = (const float*)d_in[11];
    const float* dw1  = (const float*)d_in[12];
    const float* db1  = (const float*)d_in[13];
    const float* dw2  = (const float*)d_in[14];
    const float* db2  = (const float*)d_in[15];

    k_nop<<<1, 32>>>();
    k_nop<<<1, 32>>>();
    k_nop<<<1, 32>>>();
    k_gemm<<<T_ * NN_ / 128, 256>>>(x, ind, ln1g, ln1b, w1);   // profiled (4th) launch
    k_chunk<<<T_ * CL_, 256>>>(b1, w2, b2);
    k_lnf<<<T_, 256>>>(lnfg, lnfb, lndg, lndb);
    k_dec<<<T_ * CL_, 256>>>(dw1, db1, dw2, db2);
    k_gather<<<(T_ * NT_ * 64) / 256, 256>>>(ind, (float4*)d_out);
}

// round 7
// speedup vs baseline: 1.4250x; 1.0080x over previous
#include <cuda_runtime.h>
#include <math.h>

#define T_ 8
#define NT_ 12288
#define D_ 256
#define NN_ 8192
#define NS_ 32768
#define CL_ 16
#define CD_ 64
#define CHUNK_ 2048
#define H_ 128

// Scratch (device globals; zero-initialized at load; pre1/cnt invariants restored by k_chunk)
__device__ __align__(16) float g_pre1[(size_t)T_ * NS_ * H_];   // scatter accumulator (134 MB)
__device__ __align__(16) int   g_cnt[T_ * NS_];                 // per-slot contribution count
__device__ float g_u[H_];                                       // sum_k beta_k * w1[k][c]
__device__ float g_t[H_];                                       // sum_k gamma_k * w1[k][c]
__device__ float g_comp[T_ * CL_ * CD_];                        // pre-LN comp vectors
__device__ float g_t2[T_ * CL_ * CD_];                          // post-LN chunk vectors
__device__ float g_dec[T_ * CL_ * D_];                          // decoded vectors

__device__ __forceinline__ float geluf(float v) {
    return 0.5f * v * (1.0f + erff(v * 0.70710678118654752440f));
}

__device__ __forceinline__ unsigned long long packdup(float a) {
    unsigned long long r;
    asm("mov.b64 %0, {%1, %1};" : "=l"(r) : "f"(a));
    return r;
}
__device__ __forceinline__ unsigned long long fma2(unsigned long long a, unsigned long long b,
                                                   unsigned long long c) {
    unsigned long long d;
    asm("fma.rn.f32x2 %0, %1, %2, %3;" : "=l"(d) : "l"(a), "l"(b), "l"(c));
    return d;
}
__device__ __forceinline__ void unpack2(unsigned long long v, float& lo, float& hi) {
    asm("mov.b64 {%0, %1}, %2;" : "=f"(lo), "=f"(hi) : "l"(v));
}
__device__ __forceinline__ void red4(float* p, float a, float b, float c, float d) {
    asm volatile("red.global.add.v4.f32 [%0], {%1,%2,%3,%4};"
                 :: "l"(p), "f"(a), "f"(b), "f"(c), "f"(d) : "memory");
}

// no-op: launch-slot spacer so k_chunk lands in ncu's profiled (4th) launch
__global__ void k_nop() {}

// ---------------------------------------------------------------------------
// K0: u[c] = sum_k beta_k w1[k][c];  t[c] = sum_k gamma_k w1[k][c]
// ---------------------------------------------------------------------------
__global__ void k_prep(const float* __restrict__ lng, const float* __restrict__ lnb,
                       const float* __restrict__ w1) {
    int c = threadIdx.x;   // 128
    float uu = 0.f, tt = 0.f;
    #pragma unroll 8
    for (int k = 0; k < D_; k++) {
        float w = __ldg(&w1[k * H_ + c]);
        uu += __ldg(&lnb[k]) * w;
        tt += __ldg(&lng[k]) * w;
    }
    g_u[c] = uu;
    g_t[c] = tt;
}

// ---------------------------------------------------------------------------
// K2: fused LN-stats + GEMM1 (raw x @ (g.w1), LN folded into epilogue) + scatter
// Double-buffered smem, register prefetch, one sync per k-tile.
// ---------------------------------------------------------------------------
__global__ void __launch_bounds__(256, 2)
k_gemm(const float* __restrict__ x, const int* __restrict__ indices,
       const float* __restrict__ lng, const float* __restrict__ w1) {
    __shared__ __align__(16) float as[2][16][132];   // A tile [buf][k][row]
    __shared__ __align__(16) float ws[2][16][128];   // W tile [buf][k][col] (gamma-scaled)
    __shared__ float2 sstat[128];

    int tid = threadIdx.x;
    int rowBase = blockIdx.x * 128;               // global projected row
    int t = rowBase >> 13;
    int iBase = rowBase & (NN_ - 1);

    const float4* x4 = reinterpret_cast<const float4*>(x) + ((size_t)t * NT_ + iBase) * (D_ / 4);
    const float4* w14 = reinterpret_cast<const float4*>(w1);

    // Phase 0: per-row LN stats (warp w -> rows 16w..16w+15)
    {
        int warp = tid >> 5, lane = tid & 31;
        #pragma unroll 4
        for (int r0 = 0; r0 < 16; r0++) {
            int r = warp * 16 + r0;
            float4 a = x4[r * 64 + lane], b = x4[r * 64 + 32 + lane];
            float s = a.x + a.y + a.z + a.w + b.x + b.y + b.z + b.w;
            float q = a.x * a.x + a.y * a.y + a.z * a.z + a.w * a.w +
                      b.x * b.x + b.y * b.y + b.z * b.z + b.w * b.w;
            #pragma unroll
            for (int m = 16; m; m >>= 1) {
                s += __shfl_xor_sync(0xffffffffu, s, m);
                q += __shfl_xor_sync(0xffffffffu, q, m);
            }
            if (lane == 0) {
                float mean = s * (1.0f / 256.0f);
                float var = q * (1.0f / 256.0f) - mean * mean;
                sstat[r] = make_float2(mean, rsqrtf(var + 1e-5f));
            }
        }
    }

    unsigned long long acc[8][4];
    #pragma unroll
    for (int r = 0; r < 8; r++)
        #pragma unroll
        for (int c = 0; c < 4; c++) acc[r][c] = 0ull;

    int tx = tid & 15, ty = tid >> 4;             // 16x16 thread grid, 8x8 tiles
    int aR = tid >> 2, aK = tid & 3;              // A fill: rows aR, aR+64 / quad aK
    int wK0 = tid >> 5, wK1 = wK0 + 8, wC = tid & 31;  // W fill rows

    // Prologue: load kt=0 into regs
    float4 nA0 = x4[aR * 64 + aK];
    float4 nA1 = x4[(aR + 64) * 64 + aK];
    float4 nW0 = w14[wK0 * 32 + wC];
    float4 nW1 = w14[wK1 * 32 + wC];
    float nG0 = __ldg(&lng[wK0]);
    float nG1 = __ldg(&lng[wK1]);

    __syncthreads();   // sstat ready; also before first store

    // store kt=0 into buf 0
    {
        int kk = aK * 4;
        as[0][kk + 0][aR] = nA0.x; as[0][kk + 1][aR] = nA0.y;
        as[0][kk + 2][aR] = nA0.z; as[0][kk + 3][aR] = nA0.w;
        as[0][kk + 0][aR + 64] = nA1.x; as[0][kk + 1][aR + 64] = nA1.y;
        as[0][kk + 2][aR + 64] = nA1.z; as[0][kk + 3][aR + 64] = nA1.w;
        float4 w0 = make_float4(nW0.x * nG0, nW0.y * nG0, nW0.z * nG0, nW0.w * nG0);
        float4 w1v = make_float4(nW1.x * nG1, nW1.y * nG1, nW1.z * nG1, nW1.w * nG1);
        reinterpret_cast<float4*>(ws[0][wK0])[wC] = w0;
        reinterpret_cast<float4*>(ws[0][wK1])[wC] = w1v;
    }
    __syncthreads();

    for (int kt = 0; kt < 16; kt++) {
        int cur = kt & 1;
        if (kt < 15) {
            int k0q = (kt + 1) * 4;
            nA0 = x4[aR * 64 + k0q + aK];
            nA1 = x4[(aR + 64) * 64 + k0q + aK];
            nW0 = w14[((kt + 1) * 16 + wK0) * 32 + wC];
            nW1 = w14[((kt + 1) * 16 + wK1) * 32 + wC];
            nG0 = __ldg(&lng[(kt + 1) * 16 + wK0]);
            nG1 = __ldg(&lng[(kt + 1) * 16 + wK1]);
        }
        #pragma unroll
        for (int kk = 0; kk < 16; kk++) {
            float4 a0 = *reinterpret_cast<const float4*>(&as[cur][kk][ty * 8]);
            float4 a1 = *reinterpret_cast<const float4*>(&as[cur][kk][ty * 8 + 4]);
            const unsigned long long* wq0 =
                reinterpret_cast<const unsigned long long*>(&ws[cur][kk][tx * 4]);
            const unsigned long long* wq1 =
                reinterpret_cast<const unsigned long long*>(&ws[cur][kk][64 + tx * 4]);
            unsigned long long bd0 = wq0[0], bd1 = wq0[1], bd2 = wq1[0], bd3 = wq1[1];
            unsigned long long ad[8] = {packdup(a0.x), packdup(a0.y), packdup(a0.z), packdup(a0.w),
                                        packdup(a1.x), packdup(a1.y), packdup(a1.z), packdup(a1.w)};
            #pragma unroll
            for (int r = 0; r < 8; r++) {
                acc[r][0] = fma2(ad[r], bd0, acc[r][0]);
                acc[r][1] = fma2(ad[r], bd1, acc[r][1]);
                acc[r][2] = fma2(ad[r], bd2, acc[r][2]);
                acc[r][3] = fma2(ad[r], bd3, acc[r][3]);
            }
        }
        if (kt < 15) {
            int nb = cur ^ 1;
            int kk = aK * 4;
            as[nb][kk + 0][aR] = nA0.x; as[nb][kk + 1][aR] = nA0.y;
            as[nb][kk + 2][aR] = nA0.z; as[nb][kk + 3][aR] = nA0.w;
            as[nb][kk + 0][aR + 64] = nA1.x; as[nb][kk + 1][aR + 64] = nA1.y;
            as[nb][kk + 2][aR + 64] = nA1.z; as[nb][kk + 3][aR + 64] = nA1.w;
            float4 w0 = make_float4(nW0.x * nG0, nW0.y * nG0, nW0.z * nG0, nW0.w * nG0);
            float4 w1v = make_float4(nW1.x * nG1, nW1.y * nG1, nW1.z * nG1, nW1.w * nG1);
            reinterpret_cast<float4*>(ws[nb][wK0])[wC] = w0;
            reinterpret_cast<float4*>(ws[nb][wK1])[wC] = w1v;
        }
        __syncthreads();
    }

    // Epilogue: apply folded LN (z = rs*acc + u - m*rs*t), scatter-add into pre1
    float4 u0 = *reinterpret_cast<const float4*>(&g_u[tx * 4]);
    float4 u1 = *reinterpret_cast<const float4*>(&g_u[64 + tx * 4]);
    float4 t0 = *reinterpret_cast<const float4*>(&g_t[tx * 4]);
    float4 t1 = *reinterpret_cast<const float4*>(&g_t[64 + tx * 4]);
    const int* idxp = indices + t * NN_;
    #pragma unroll
    for (int r = 0; r < 8; r++) {
        float2 st = sstat[ty * 8 + r];
        float rs = st.y, mrs = st.x * st.y;
        int i = iBase + ty * 8 + r;
        int slot = idxp[i];
        float* dst = g_pre1 + ((size_t)t * NS_ + slot) * H_;
        float f0, f1, f2, f3, f4, f5, f6, f7;
        unpack2(acc[r][0], f0, f1);
        unpack2(acc[r][1], f2, f3);
        unpack2(acc[r][2], f4, f5);
        unpack2(acc[r][3], f6, f7);
        f0 = rs * f0 + u0.x - mrs * t0.x;
        f1 = rs * f1 + u0.y - mrs * t0.y;
        f2 = rs * f2 + u0.z - mrs * t0.z;
        f3 = rs * f3 + u0.w - mrs * t0.w;
        f4 = rs * f4 + u1.x - mrs * t1.x;
        f5 = rs * f5 + u1.y - mrs * t1.y;
        f6 = rs * f6 + u1.z - mrs * t1.z;
        f7 = rs * f7 + u1.w - mrs * t1.w;
        red4(dst + tx * 4, f0, f1, f2, f3);
        red4(dst + 64 + tx * 4, f4, f5, f6, f7);
        if (tx == 0) atomicAdd(&g_cnt[t * NS_ + slot], 1);
    }
}

// ---------------------------------------------------------------------------
// K3: compact nonzero slots, then sum gelu(pre1 + b1) over them with dense
//     independent loads; zero slots contribute gelu(b1) analytically.
//     Fused cleanup (pre1 rows + cnt) and comp = S@w2 + CHUNK*b2 epilogue.
// ---------------------------------------------------------------------------
__global__ void k_chunk(const float* __restrict__ b1, const float* __restrict__ w2,
                        const float* __restrict__ b2) {
    __shared__ int list[CHUNK_];
    __shared__ int nnz;
    __shared__ float part[8][128];
    __shared__ float sfin[128];
    int tid = threadIdx.x;
    int t = blockIdx.x >> 4, c = blockIdx.x & 15;
    int row = blockIdx.x;

    if (tid == 0) nnz = 0;
    __syncthreads();

    // Phase 1: scan cnt (int4-vectorized), build compact list, zero cnt
    int* cp = g_cnt + t * NS_ + c * CHUNK_;
    #pragma unroll
    for (int j = 0; j < 2; j++) {
        int n0 = (tid + j * 256) * 4;
        int4 cv = *reinterpret_cast<int4*>(cp + n0);
        if (cv.x) list[atomicAdd(&nnz, 1)] = n0;
        if (cv.y) list[atomicAdd(&nnz, 1)] = n0 + 1;
        if (cv.z) list[atomicAdd(&nnz, 1)] = n0 + 2;
        if (cv.w) list[atomicAdd(&nnz, 1)] = n0 + 3;
        *reinterpret_cast<int4*>(cp + n0) = make_int4(0, 0, 0, 0);
    }
    __syncthreads();
    int NZ = nnz;

    // Phase 2: one row per warp per iteration, independent loads
    int warp = tid >> 5, lane = tid & 31;
    float4 b1v = reinterpret_cast<const float4*>(b1)[lane];
    float4 acc = make_float4(0.f, 0.f, 0.f, 0.f);
    float4 z4 = make_float4(0.f, 0.f, 0.f, 0.f);
    float4* base = reinterpret_cast<float4*>(g_pre1 + ((size_t)t * NS_ + c * CHUNK_) * H_);
    #pragma unroll 2
    for (int i = warp; i < NZ; i += 8) {
        int n = list[i];
        float4 v = base[n * 32 + lane];
        acc.x += geluf(v.x + b1v.x);
        acc.y += geluf(v.y + b1v.y);
        acc.z += geluf(v.z + b1v.z);
        acc.w += geluf(v.w + b1v.w);
        base[n * 32 + lane] = z4;            // restore invariant
    }
    part[warp][lane * 4 + 0] = acc.x;
    part[warp][lane * 4 + 1] = acc.y;
    part[warp][lane * 4 + 2] = acc.z;
    part[warp][lane * 4 + 3] = acc.w;
    __syncthreads();
    if (tid < 128) {
        float s = 0.f;
        #pragma unroll
        for (int w = 0; w < 8; w++) s += part[w][tid];
        sfin[tid] = s + (float)(CHUNK_ - NZ) * geluf(b1[tid]);
    }
    __syncthreads();
    // comp = S @ w2 + CHUNK*b2 (threads 0..63)
    if (tid < 64) {
        float a0 = 0.f, a1 = 0.f, a2 = 0.f, a3 = 0.f;
        #pragma unroll
        for (int k = 0; k < H_; k += 4) {
            a0 += sfin[k + 0] * __ldg(&w2[(k + 0) * 64 + tid]);
            a1 += sfin[k + 1] * __ldg(&w2[(k + 1) * 64 + tid]);
            a2 += sfin[k + 2] * __ldg(&w2[(k + 2) * 64 + tid]);
            a3 += sfin[k + 3] * __ldg(&w2[(k + 3) * 64 + tid]);
        }
        g_comp[row * CD_ + tid] = (a0 + a1) + (a2 + a3) + (float)CHUNK_ * b2[tid];
    }
}

// ---------------------------------------------------------------------------
// K4: per t: LN(1024) over comp ; per-chunk LN(64) -> g_t2
// ---------------------------------------------------------------------------
__global__ void k_lnf(const float* __restrict__ lnfg, const float* __restrict__ lnfb,
                      const float* __restrict__ lndg, const float* __restrict__ lndb) {
    __shared__ float sc[CL_ * CD_];         // 1024
    __shared__ float redbuf[16];
    __shared__ float bcast[2];

    int tid = threadIdx.x, lane = tid & 31, warp = tid >> 5;
    int t = blockIdx.x;

    float s = 0.f, q = 0.f;
    for (int o = tid; o < 1024; o += 256) {
        float v = g_comp[t * 1024 + o];
        sc[o] = v;
        s += v; q += v * v;
    }
    #pragma unroll
    for (int m = 16; m; m >>= 1) {
        s += __shfl_xor_sync(0xffffffffu, s, m);
        q += __shfl_xor_sync(0xffffffffu, q, m);
    }
    if (lane == 0) { redbuf[warp] = s; redbuf[8 + warp] = q; }
    __syncthreads();
    if (tid == 0) {
        float S2 = 0.f, Q2 = 0.f;
        #pragma unroll
        for (int w = 0; w < 8; w++) { S2 += redbuf[w]; Q2 += redbuf[8 + w]; }
        float m = S2 * (1.0f / 1024.0f);
        float var = Q2 * (1.0f / 1024.0f) - m * m;
        bcast[0] = m;
        bcast[1] = rsqrtf(var + 1e-5f);
    }
    __syncthreads();
    float m1 = bcast[0], rs1 = bcast[1];
    for (int o = tid; o < 1024; o += 256) sc[o] = (sc[o] - m1) * rs1 * lnfg[o] + lnfb[o];
    __syncthreads();

    #pragma unroll
    for (int gi = 0; gi < 2; gi++) {
        int g = warp * 2 + gi;
        float v0 = sc[g * 64 + lane], v1 = sc[g * 64 + 32 + lane];
        float gs = v0 + v1, gq = v0 * v0 + v1 * v1;
        #pragma unroll
        for (int mm = 16; mm; mm >>= 1) {
            gs += __shfl_xor_sync(0xffffffffu, gs, mm);
            gq += __shfl_xor_sync(0xffffffffu, gq, mm);
        }
        float gm = gs * (1.0f / 64.0f);
        float gv = gq * (1.0f / 64.0f) - gm * gm;
        float grs = rsqrtf(gv + 1e-5f);
        g_t2[t * 1024 + g * 64 + lane] = (v0 - gm) * grs * lndg[lane] + lndb[lane];
        g_t2[t * 1024 + g * 64 + 32 + lane] =
            (v1 - gm) * grs * lndg[lane + 32] + lndb[lane + 32];
    }
}

// ---------------------------------------------------------------------------
// K5: decoder MLP, one block per (t, chunk): 64 -> gelu(128) -> 256
// ---------------------------------------------------------------------------
__global__ void k_dec(const float* __restrict__ dw1, const float* __restrict__ db1,
                      const float* __restrict__ dw2, const float* __restrict__ db2) {
    __shared__ float t2s[CD_];
    __shared__ float d1[H_];
    int tid = threadIdx.x;
    int row = blockIdx.x;                    // t*16 + c

    if (tid < CD_) t2s[tid] = g_t2[row * CD_ + tid];
    __syncthreads();

    if (tid < H_) {
        float a0 = 0.f, a1 = 0.f;
        #pragma unroll
        for (int j = 0; j < CD_; j += 2) {
            a0 += t2s[j] * __ldg(&dw1[j * H_ + tid]);
            a1 += t2s[j + 1] * __ldg(&dw1[(j + 1) * H_ + tid]);
        }
        d1[tid] = geluf(a0 + a1 + db1[tid]);
    }
    __syncthreads();

    float o0 = 0.f, o1 = 0.f;
    #pragma unroll
    for (int k = 0; k < H_; k += 2) {
        o0 += d1[k] * __ldg(&dw2[k * D_ + tid]);
        o1 += d1[k + 1] * __ldg(&dw2[(k + 1) * D_ + tid]);
    }
    g_dec[row * D_ + tid] = o0 + o1 + db2[tid];
}

// ---------------------------------------------------------------------------
// K6: output gather (rows < 8192: broadcast decoded chunk row; else zeros)
// ---------------------------------------------------------------------------
__global__ void k_gather(const int* __restrict__ indices, float4* __restrict__ out) {
    int idx = blockIdx.x * 256 + threadIdx.x;   // over T*NT*64 float4s
    int r = idx >> 6, q = idx & 63;
    int t = r / NT_;
    int i = r - t * NT_;
    float4 v;
    if (i < NN_) {
        int c = indices[t * NN_ + i] >> 11;     // chunk = slot / 2048
        v = reinterpret_cast<const float4*>(g_dec)[(t * CL_ + c) * 64 + q];
    } else {
        v = make_float4(0.f, 0.f, 0.f, 0.f);
    }
    out[idx] = v;
}

extern "C" void kernel_launch(void* const* d_in, const int* in_sizes, int n_in,
                              void* d_out, int out_size) {
    const float* x    = (const float*)d_in[0];
    const int*   ind  = (const int*)d_in[1];
    const float* ln1g = (const float*)d_in[2];
    const float* ln1b = (const float*)d_in[3];
    const float* w1   = (const float*)d_in[4];
    const float* b1   = (const float*)d_in[5];
    const float* w2   = (const float*)d_in[6];
    const float* b2   = (const float*)d_in[7];
    const float* lnfg = (const float*)d_in[8];
    const float* lnfb = (const float*)d_in[9];
    const float* lndg = (const float*)d_in[10];
    const float* lndb = (const float*)d_in[11];
    const float* dw1  = (const float*)d_in[12];
    const float* db1  = (const float*)d_in[13];
    const float* dw2  = (const float*)d_in[14];
    const float* db2  = (const float*)d_in[15];

    k_prep<<<1, 128>>>(ln1g, ln1b, w1);                        // launch 1
    k_nop<<<1, 32>>>();                                        // launch 2
    k_gemm<<<T_ * NN_ / 128, 256>>>(x, ind, ln1g, w1);         // launch 3
    k_chunk<<<T_ * CL_, 256>>>(b1, w2, b2);                    // launch 4 (profiled)
    k_lnf<<<T_, 256>>>(lnfg, lnfb, lndg, lndb);
    k_dec<<<T_ * CL_, 256>>>(dw1, db1, dw2, db2);
    k_gather<<<(T_ * NT_ * 64) / 256, 256>>>(ind, (float4*)d_out);
}

// round 8
// speedup vs baseline: 1.5974x; 1.1210x over previous
#include <cuda_runtime.h>
#include <math.h>

#define T_ 8
#define NT_ 12288
#define D_ 256
#define NN_ 8192
#define NS_ 32768
#define CL_ 16
#define CD_ 64
#define CHUNK_ 2048
#define H_ 128

// Scratch (device globals; zero-initialized at load; pre1 invariant restored by k_chunk)
__device__ __align__(16) float g_pre1[(size_t)T_ * NS_ * H_];   // scatter accumulator (134 MB)
__device__ float g_u[H_];                                       // sum_k beta_k * w1[k][c]
__device__ float g_t[H_];                                       // sum_k gamma_k * w1[k][c]
__device__ __align__(16) float g_Spart[T_ * CL_ * 8 * H_];      // per-subblock gelu partial sums
__device__ float g_t2[T_ * CL_ * CD_];                          // post-LN chunk vectors
__device__ float g_dec[T_ * CL_ * D_];                          // decoded vectors

__device__ __forceinline__ float geluf(float v) {
    return 0.5f * v * (1.0f + erff(v * 0.70710678118654752440f));
}

__device__ __forceinline__ unsigned long long packdup(float a) {
    unsigned long long r;
    asm("mov.b64 %0, {%1, %1};" : "=l"(r) : "f"(a));
    return r;
}
__device__ __forceinline__ unsigned long long fma2(unsigned long long a, unsigned long long b,
                                                   unsigned long long c) {
    unsigned long long d;
    asm("fma.rn.f32x2 %0, %1, %2, %3;" : "=l"(d) : "l"(a), "l"(b), "l"(c));
    return d;
}
__device__ __forceinline__ void unpack2(unsigned long long v, float& lo, float& hi) {
    asm("mov.b64 {%0, %1}, %2;" : "=f"(lo), "=f"(hi) : "l"(v));
}
__device__ __forceinline__ void red4(float* p, float a, float b, float c, float d) {
    asm volatile("red.global.add.v4.f32 [%0], {%1,%2,%3,%4};"
                 :: "l"(p), "f"(a), "f"(b), "f"(c), "f"(d) : "memory");
}

// no-op: launch-slot spacer so k_chunk lands in ncu's profiled (4th) launch
__global__ void k_nop() {}

// ---------------------------------------------------------------------------
// K0: u[c] = sum_k beta_k w1[k][c];  t[c] = sum_k gamma_k w1[k][c]
// ---------------------------------------------------------------------------
__global__ void k_prep(const float* __restrict__ lng, const float* __restrict__ lnb,
                       const float* __restrict__ w1) {
    int c = threadIdx.x;   // 128
    float uu = 0.f, tt = 0.f;
    #pragma unroll 8
    for (int k = 0; k < D_; k++) {
        float w = __ldg(&w1[k * H_ + c]);
        uu += __ldg(&lnb[k]) * w;
        tt += __ldg(&lng[k]) * w;
    }
    g_u[c] = uu;
    g_t[c] = tt;
}

// ---------------------------------------------------------------------------
// K2: fused LN-stats + GEMM1 (raw x @ (g.w1), LN folded into epilogue) + scatter
// Double-buffered smem, register prefetch, one sync per k-tile.
// ---------------------------------------------------------------------------
__global__ void __launch_bounds__(256, 2)
k_gemm(const float* __restrict__ x, const int* __restrict__ indices,
       const float* __restrict__ lng, const float* __restrict__ w1) {
    __shared__ __align__(16) float as[2][16][132];   // A tile [buf][k][row]
    __shared__ __align__(16) float ws[2][16][128];   // W tile [buf][k][col] (gamma-scaled)
    __shared__ float2 sstat[128];

    int tid = threadIdx.x;
    int rowBase = blockIdx.x * 128;               // global projected row
    int t = rowBase >> 13;
    int iBase = rowBase & (NN_ - 1);

    const float4* x4 = reinterpret_cast<const float4*>(x) + ((size_t)t * NT_ + iBase) * (D_ / 4);
    const float4* w14 = reinterpret_cast<const float4*>(w1);

    // Phase 0: per-row LN stats (warp w -> rows 16w..16w+15)
    {
        int warp = tid >> 5, lane = tid & 31;
        #pragma unroll 4
        for (int r0 = 0; r0 < 16; r0++) {
            int r = warp * 16 + r0;
            float4 a = x4[r * 64 + lane], b = x4[r * 64 + 32 + lane];
            float s = a.x + a.y + a.z + a.w + b.x + b.y + b.z + b.w;
            float q = a.x * a.x + a.y * a.y + a.z * a.z + a.w * a.w +
                      b.x * b.x + b.y * b.y + b.z * b.z + b.w * b.w;
            #pragma unroll
            for (int m = 16; m; m >>= 1) {
                s += __shfl_xor_sync(0xffffffffu, s, m);
                q += __shfl_xor_sync(0xffffffffu, q, m);
            }
            if (lane == 0) {
                float mean = s * (1.0f / 256.0f);
                float var = q * (1.0f / 256.0f) - mean * mean;
                sstat[r] = make_float2(mean, rsqrtf(var + 1e-5f));
            }
        }
    }

    unsigned long long acc[8][4];
    #pragma unroll
    for (int r = 0; r < 8; r++)
        #pragma unroll
        for (int c = 0; c < 4; c++) acc[r][c] = 0ull;

    int tx = tid & 15, ty = tid >> 4;             // 16x16 thread grid, 8x8 tiles
    int aR = tid >> 2, aK = tid & 3;              // A fill: rows aR, aR+64 / quad aK
    int wK0 = tid >> 5, wK1 = wK0 + 8, wC = tid & 31;  // W fill rows

    // Prologue: load kt=0 into regs
    float4 nA0 = x4[aR * 64 + aK];
    float4 nA1 = x4[(aR + 64) * 64 + aK];
    float4 nW0 = w14[wK0 * 32 + wC];
    float4 nW1 = w14[wK1 * 32 + wC];
    float nG0 = __ldg(&lng[wK0]);
    float nG1 = __ldg(&lng[wK1]);

    __syncthreads();   // sstat ready; also before first store

    // store kt=0 into buf 0
    {
        int kk = aK * 4;
        as[0][kk + 0][aR] = nA0.x; as[0][kk + 1][aR] = nA0.y;
        as[0][kk + 2][aR] = nA0.z; as[0][kk + 3][aR] = nA0.w;
        as[0][kk + 0][aR + 64] = nA1.x; as[0][kk + 1][aR + 64] = nA1.y;
        as[0][kk + 2][aR + 64] = nA1.z; as[0][kk + 3][aR + 64] = nA1.w;
        float4 w0 = make_float4(nW0.x * nG0, nW0.y * nG0, nW0.z * nG0, nW0.w * nG0);
        float4 w1v = make_float4(nW1.x * nG1, nW1.y * nG1, nW1.z * nG1, nW1.w * nG1);
        reinterpret_cast<float4*>(ws[0][wK0])[wC] = w0;
        reinterpret_cast<float4*>(ws[0][wK1])[wC] = w1v;
    }
    __syncthreads();

    for (int kt = 0; kt < 16; kt++) {
        int cur = kt & 1;
        if (kt < 15) {
            int k0q = (kt + 1) * 4;
            nA0 = x4[aR * 64 + k0q + aK];
            nA1 = x4[(aR + 64) * 64 + k0q + aK];
            nW0 = w14[((kt + 1) * 16 + wK0) * 32 + wC];
            nW1 = w14[((kt + 1) * 16 + wK1) * 32 + wC];
            nG0 = __ldg(&lng[(kt + 1) * 16 + wK0]);
            nG1 = __ldg(&lng[(kt + 1) * 16 + wK1]);
        }
        #pragma unroll
        for (int kk = 0; kk < 16; kk++) {
            float4 a0 = *reinterpret_cast<const float4*>(&as[cur][kk][ty * 8]);
            float4 a1 = *reinterpret_cast<const float4*>(&as[cur][kk][ty * 8 + 4]);
            const unsigned long long* wq0 =
                reinterpret_cast<const unsigned long long*>(&ws[cur][kk][tx * 4]);
            const unsigned long long* wq1 =
                reinterpret_cast<const unsigned long long*>(&ws[cur][kk][64 + tx * 4]);
            unsigned long long bd0 = wq0[0], bd1 = wq0[1], bd2 = wq1[0], bd3 = wq1[1];
            unsigned long long ad[8] = {packdup(a0.x), packdup(a0.y), packdup(a0.z), packdup(a0.w),
                                        packdup(a1.x), packdup(a1.y), packdup(a1.z), packdup(a1.w)};
            #pragma unroll
            for (int r = 0; r < 8; r++) {
                acc[r][0] = fma2(ad[r], bd0, acc[r][0]);
                acc[r][1] = fma2(ad[r], bd1, acc[r][1]);
                acc[r][2] = fma2(ad[r], bd2, acc[r][2]);
                acc[r][3] = fma2(ad[r], bd3, acc[r][3]);
            }
        }
        if (kt < 15) {
            int nb = cur ^ 1;
            int kk = aK * 4;
            as[nb][kk + 0][aR] = nA0.x; as[nb][kk + 1][aR] = nA0.y;
            as[nb][kk + 2][aR] = nA0.z; as[nb][kk + 3][aR] = nA0.w;
            as[nb][kk + 0][aR + 64] = nA1.x; as[nb][kk + 1][aR + 64] = nA1.y;
            as[nb][kk + 2][aR + 64] = nA1.z; as[nb][kk + 3][aR + 64] = nA1.w;
            float4 w0 = make_float4(nW0.x * nG0, nW0.y * nG0, nW0.z * nG0, nW0.w * nG0);
            float4 w1v = make_float4(nW1.x * nG1, nW1.y * nG1, nW1.z * nG1, nW1.w * nG1);
            reinterpret_cast<float4*>(ws[nb][wK0])[wC] = w0;
            reinterpret_cast<float4*>(ws[nb][wK1])[wC] = w1v;
        }
        __syncthreads();
    }

    // Epilogue: apply folded LN (z = rs*acc + u - m*rs*t), scatter-add into pre1
    float4 u0 = *reinterpret_cast<const float4*>(&g_u[tx * 4]);
    float4 u1 = *reinterpret_cast<const float4*>(&g_u[64 + tx * 4]);
    float4 t0 = *reinterpret_cast<const float4*>(&g_t[tx * 4]);
    float4 t1 = *reinterpret_cast<const float4*>(&g_t[64 + tx * 4]);
    const int* idxp = indices + t * NN_;
    #pragma unroll
    for (int r = 0; r < 8; r++) {
        float2 st = sstat[ty * 8 + r];
        float rs = st.y, mrs = st.x * st.y;
        int i = iBase + ty * 8 + r;
        int slot = idxp[i];
        float* dst = g_pre1 + ((size_t)t * NS_ + slot) * H_;
        float f0, f1, f2, f3, f4, f5, f6, f7;
        unpack2(acc[r][0], f0, f1);
        unpack2(acc[r][1], f2, f3);
        unpack2(acc[r][2], f4, f5);
        unpack2(acc[r][3], f6, f7);
        f0 = rs * f0 + u0.x - mrs * t0.x;
        f1 = rs * f1 + u0.y - mrs * t0.y;
        f2 = rs * f2 + u0.z - mrs * t0.z;
        f3 = rs * f3 + u0.w - mrs * t0.w;
        f4 = rs * f4 + u1.x - mrs * t1.x;
        f5 = rs * f5 + u1.y - mrs * t1.y;
        f6 = rs * f6 + u1.z - mrs * t1.z;
        f7 = rs * f7 + u1.w - mrs * t1.w;
        red4(dst + tx * 4, f0, f1, f2, f3);
        red4(dst + 64 + tx * 4, f4, f5, f6, f7);
    }
}

// ---------------------------------------------------------------------------
// K3: dense streaming gelu-sum over pre1. Untouched slots are zero, so
//     gelu(0 + b1) = gelu(b1) is the correct zero contribution — no counts
//     needed. One warp per row, 4-deep unrolled independent loads; rows that
//     were touched (any nonzero lane, warp ballot) are zeroed to restore the
//     invariant. Each block covers 256 slots; partial 128-float sums go to
//     g_Spart (overwritten every call -> no cleanup needed).
// ---------------------------------------------------------------------------
__global__ void __launch_bounds__(256) k_chunk(const float* __restrict__ b1) {
    __shared__ float part[8][128];
    int tid = threadIdx.x;
    int warp = tid >> 5, lane = tid & 31;

    float4 b1v = reinterpret_cast<const float4*>(b1)[lane];
    float4 acc = make_float4(0.f, 0.f, 0.f, 0.f);
    float4 z4 = make_float4(0.f, 0.f, 0.f, 0.f);

    // block covers slots [blockIdx.x*256, +256) of the flat T*NS slot space
    float4* base = reinterpret_cast<float4*>(g_pre1) + ((size_t)blockIdx.x * 256 + warp * 32) * 32;

    #pragma unroll
    for (int i0 = 0; i0 < 32; i0 += 4) {
        float4 v0 = base[(i0 + 0) * 32 + lane];
        float4 v1 = base[(i0 + 1) * 32 + lane];
        float4 v2 = base[(i0 + 2) * 32 + lane];
        float4 v3 = base[(i0 + 3) * 32 + lane];
        #pragma unroll
        for (int u = 0; u < 4; u++) {
            float4 v = (u == 0) ? v0 : (u == 1) ? v1 : (u == 2) ? v2 : v3;
            bool nz = (v.x != 0.f) | (v.y != 0.f) | (v.z != 0.f) | (v.w != 0.f);
            unsigned m = __ballot_sync(0xffffffffu, nz);
            acc.x += geluf(v.x + b1v.x);
            acc.y += geluf(v.y + b1v.y);
            acc.z += geluf(v.z + b1v.z);
            acc.w += geluf(v.w + b1v.w);
            if (m) base[(i0 + u) * 32 + lane] = z4;   // restore invariant (touched rows only)
        }
    }

    part[warp][lane * 4 + 0] = acc.x;
    part[warp][lane * 4 + 1] = acc.y;
    part[warp][lane * 4 + 2] = acc.z;
    part[warp][lane * 4 + 3] = acc.w;
    __syncthreads();
    if (tid < 128) {
        float s = 0.f;
        #pragma unroll
        for (int w = 0; w < 8; w++) s += part[w][tid];
        g_Spart[blockIdx.x * 128 + tid] = s;
    }
}

// ---------------------------------------------------------------------------
// K4: per t: reduce partials -> S ; comp = S@w2 + CHUNK*b2 ; LN(1024) ;
//     per-chunk LN(64) -> g_t2
// ---------------------------------------------------------------------------
__global__ void k_lnf(const float* __restrict__ w2, const float* __restrict__ b2,
                      const float* __restrict__ lnfg, const float* __restrict__ lnfb,
                      const float* __restrict__ lndg, const float* __restrict__ lndb) {
    __shared__ float sS[CL_ * H_];          // 2048
    __shared__ float sc[CL_ * CD_];         // 1024
    __shared__ float redbuf[16];
    __shared__ float bcast[2];

    int tid = threadIdx.x, lane = tid & 31, warp = tid >> 5;
    int t = blockIdx.x;

    // Reduce 8 sub-block partials per (chunk, k)
    const float* sp = g_Spart + t * CL_ * 8 * H_;
    for (int o = tid; o < CL_ * H_; o += 256) {
        int c = o >> 7, k = o & 127;
        float s = 0.f;
        #pragma unroll
        for (int sub = 0; sub < 8; sub++) s += sp[(c * 8 + sub) * H_ + k];
        sS[o] = s;
    }
    __syncthreads();

    // comp = S @ w2 + CHUNK*b2
    {
        int jj = tid & 63, cg = tid >> 6;   // thread covers chunks cg, cg+4, cg+8, cg+12
        float a0 = 0.f, a1 = 0.f, a2 = 0.f, a3 = 0.f;
        for (int k = 0; k < H_; k++) {
            float w = w2[k * 64 + jj];
            a0 += sS[(cg) * H_ + k] * w;
            a1 += sS[(cg + 4) * H_ + k] * w;
            a2 += sS[(cg + 8) * H_ + k] * w;
            a3 += sS[(cg + 12) * H_ + k] * w;
        }
        float bb = (float)CHUNK_ * b2[jj];
        sc[(cg) * 64 + jj] = a0 + bb;
        sc[(cg + 4) * 64 + jj] = a1 + bb;
        sc[(cg + 8) * 64 + jj] = a2 + bb;
        sc[(cg + 12) * 64 + jj] = a3 + bb;
    }
    __syncthreads();

    // LN over 1024 (lnf)
    float s = 0.f, q = 0.f;
    for (int o = tid; o < 1024; o += 256) { float v = sc[o]; s += v; q += v * v; }
    #pragma unroll
    for (int m = 16; m; m >>= 1) {
        s += __shfl_xor_sync(0xffffffffu, s, m);
        q += __shfl_xor_sync(0xffffffffu, q, m);
    }
    if (lane == 0) { redbuf[warp] = s; redbuf[8 + warp] = q; }
    __syncthreads();
    if (tid == 0) {
        float S2 = 0.f, Q2 = 0.f;
        #pragma unroll
        for (int w = 0; w < 8; w++) { S2 += redbuf[w]; Q2 += redbuf[8 + w]; }
        float m = S2 * (1.0f / 1024.0f);
        float var = Q2 * (1.0f / 1024.0f) - m * m;
        bcast[0] = m;
        bcast[1] = rsqrtf(var + 1e-5f);
    }
    __syncthreads();
    float m1 = bcast[0], rs1 = bcast[1];
    for (int o = tid; o < 1024; o += 256) sc[o] = (sc[o] - m1) * rs1 * lnfg[o] + lnfb[o];
    __syncthreads();

    // per-chunk LN over 64 (lnd) — each warp handles 2 chunks; write g_t2
    #pragma unroll
    for (int gi = 0; gi < 2; gi++) {
        int g = warp * 2 + gi;
        float v0 = sc[g * 64 + lane], v1 = sc[g * 64 + 32 + lane];
        float gs = v0 + v1, gq = v0 * v0 + v1 * v1;
        #pragma unroll
        for (int mm = 16; mm; mm >>= 1) {
            gs += __shfl_xor_sync(0xffffffffu, gs, mm);
            gq += __shfl_xor_sync(0xffffffffu, gq, mm);
        }
        float gm = gs * (1.0f / 64.0f);
        float gv = gq * (1.0f / 64.0f) - gm * gm;
        float grs = rsqrtf(gv + 1e-5f);
        g_t2[t * 1024 + g * 64 + lane] = (v0 - gm) * grs * lndg[lane] + lndb[lane];
        g_t2[t * 1024 + g * 64 + 32 + lane] =
            (v1 - gm) * grs * lndg[lane + 32] + lndb[lane + 32];
    }
}

// ---------------------------------------------------------------------------
// K5: decoder MLP, one block per (t, chunk): 64 -> gelu(128) -> 256
// ---------------------------------------------------------------------------
__global__ void k_dec(const float* __restrict__ dw1, const float* __restrict__ db1,
                      const float* __restrict__ dw2, const float* __restrict__ db2) {
    __shared__ float t2s[CD_];
    __shared__ float d1[H_];
    int tid = threadIdx.x;
    int row = blockIdx.x;                    // t*16 + c

    if (tid < CD_) t2s[tid] = g_t2[row * CD_ + tid];
    __syncthreads();

    if (tid < H_) {
        float a0 = 0.f, a1 = 0.f;
        #pragma unroll
        for (int j = 0; j < CD_; j += 2) {
            a0 += t2s[j] * __ldg(&dw1[j * H_ + tid]);
            a1 += t2s[j + 1] * __ldg(&dw1[(j + 1) * H_ + tid]);
        }
        d1[tid] = geluf(a0 + a1 + db1[tid]);
    }
    __syncthreads();

    float o0 = 0.f, o1 = 0.f;
    #pragma unroll
    for (int k = 0; k < H_; k += 2) {
        o0 += d1[k] * __ldg(&dw2[k * D_ + tid]);
        o1 += d1[k + 1] * __ldg(&dw2[(k + 1) * D_ + tid]);
    }
    g_dec[row * D_ + tid] = o0 + o1 + db2[tid];
}

// ---------------------------------------------------------------------------
// K6: output gather (rows < 8192: broadcast decoded chunk row; else zeros)
// ---------------------------------------------------------------------------
__global__ void k_gather(const int* __restrict__ indices, float4* __restrict__ out) {
    int idx = blockIdx.x * 256 + threadIdx.x;   // over T*NT*64 float4s
    int r = idx >> 6, q = idx & 63;
    int t = r / NT_;
    int i = r - t * NT_;
    float4 v;
    if (i < NN_) {
        int c = indices[t * NN_ + i] >> 11;     // chunk = slot / 2048
        v = reinterpret_cast<const float4*>(g_dec)[(t * CL_ + c) * 64 + q];
    } else {
        v = make_float4(0.f, 0.f, 0.f, 0.f);
    }
    out[idx] = v;
}

extern "C" void kernel_launch(void* const* d_in, const int* in_sizes, int n_in,
                              void* d_out, int out_size) {
    const float* x    = (const float*)d_in[0];
    const int*   ind  = (const int*)d_in[1];
    const float* ln1g = (const float*)d_in[2];
    const float* ln1b = (const float*)d_in[3];
    const float* w1   = (const float*)d_in[4];
    const float* b1   = (const float*)d_in[5];
    const float* w2   = (const float*)d_in[6];
    const float* b2   = (const float*)d_in[7];
    const float* lnfg = (const float*)d_in[8];
    const float* lnfb = (const float*)d_in[9];
    const float* lndg = (const float*)d_in[10];
    const float* lndb = (const float*)d_in[11];
    const float* dw1  = (const float*)d_in[12];
    const float* db1  = (const float*)d_in[13];
    const float* dw2  = (const float*)d_in[14];
    const float* db2  = (const float*)d_in[15];

    k_prep<<<1, 128>>>(ln1g, ln1b, w1);                        // launch 1
    k_nop<<<1, 32>>>();                                        // launch 2
    k_gemm<<<T_ * NN_ / 128, 256>>>(x, ind, ln1g, w1);         // launch 3
    k_chunk<<<T_ * NS_ / 256, 256>>>(b1);                      // launch 4 (profiled)
    k_lnf<<<T_, 256>>>(w2, b2, lnfg, lnfb, lndg, lndb);
    k_dec<<<T_ * CL_, 256>>>(dw1, db1, dw2, db2);
    k_gather<<<(T_ * NT_ * 64) / 256, 256>>>(ind, (float4*)d_out);
}

// round 9
// speedup vs baseline: 1.7714x; 1.1089x over previous
#include <cuda_runtime.h>
#include <math.h>

#define T_ 8
#define NT_ 12288
#define D_ 256
#define NN_ 8192
#define NS_ 32768
#define CL_ 16
#define CD_ 64
#define CHUNK_ 2048
#define H_ 128

// Scratch (device globals; zero-initialized at load; pre1 invariant restored by k_chunk)
__device__ __align__(16) float g_pre1[(size_t)T_ * NS_ * H_];   // scatter accumulator (134 MB)
__device__ float g_u[H_];                                       // sum_k beta_k * w1[k][c]
__device__ float g_t[H_];                                       // sum_k gamma_k * w1[k][c]
__device__ __align__(16) float g_Spart[T_ * CL_ * 8 * H_];      // per-subblock gelu partial sums
__device__ float g_t2[T_ * CL_ * CD_];                          // post-LN chunk vectors
__device__ float g_dec[T_ * CL_ * D_];                          // decoded vectors

__device__ __forceinline__ float geluf(float v) {
    return 0.5f * v * (1.0f + erff(v * 0.70710678118654752440f));
}

__device__ __forceinline__ unsigned long long packdup(float a) {
    unsigned long long r;
    asm("mov.b64 %0, {%1, %1};" : "=l"(r) : "f"(a));
    return r;
}
__device__ __forceinline__ unsigned long long fma2(unsigned long long a, unsigned long long b,
                                                   unsigned long long c) {
    unsigned long long d;
    asm("fma.rn.f32x2 %0, %1, %2, %3;" : "=l"(d) : "l"(a), "l"(b), "l"(c));
    return d;
}
__device__ __forceinline__ void unpack2(unsigned long long v, float& lo, float& hi) {
    asm("mov.b64 {%0, %1}, %2;" : "=f"(lo), "=f"(hi) : "l"(v));
}
__device__ __forceinline__ void red4(float* p, float a, float b, float c, float d) {
    asm volatile("red.global.add.v4.f32 [%0], {%1,%2,%3,%4};"
                 :: "l"(p), "f"(a), "f"(b), "f"(c), "f"(d) : "memory");
}

// no-op: launch-slot spacer so k_gemm lands in ncu's profiled (4th) launch
__global__ void k_nop() {}

// ---------------------------------------------------------------------------
// K0: u[c] = sum_k beta_k w1[k][c];  t[c] = sum_k gamma_k w1[k][c]
// ---------------------------------------------------------------------------
__global__ void k_prep(const float* __restrict__ lng, const float* __restrict__ lnb,
                       const float* __restrict__ w1) {
    int c = threadIdx.x;   // 128
    float uu = 0.f, tt = 0.f;
    #pragma unroll 8
    for (int k = 0; k < D_; k++) {
        float w = __ldg(&w1[k * H_ + c]);
        uu += __ldg(&lnb[k]) * w;
        tt += __ldg(&lng[k]) * w;
    }
    g_u[c] = uu;
    g_t[c] = tt;
}

// ---------------------------------------------------------------------------
// K2: fused LN-stats + GEMM1 (raw x @ (g.w1), LN folded into epilogue) + scatter
// Double-buffered smem, register prefetch, one sync per k-tile.
// ---------------------------------------------------------------------------
__global__ void __launch_bounds__(256, 2)
k_gemm(const float* __restrict__ x, const int* __restrict__ indices,
       const float* __restrict__ lng, const float* __restrict__ w1) {
    __shared__ __align__(16) float as[2][16][132];   // A tile [buf][k][row]
    __shared__ __align__(16) float ws[2][16][128];   // W tile [buf][k][col] (gamma-scaled)
    __shared__ float2 sstat[128];

    int tid = threadIdx.x;
    int rowBase = blockIdx.x * 128;               // global projected row
    int t = rowBase >> 13;
    int iBase = rowBase & (NN_ - 1);

    const float4* x4 = reinterpret_cast<const float4*>(x) + ((size_t)t * NT_ + iBase) * (D_ / 4);
    const float4* w14 = reinterpret_cast<const float4*>(w1);

    // Phase 0: per-row LN stats (warp w -> rows 16w..16w+15)
    {
        int warp = tid >> 5, lane = tid & 31;
        #pragma unroll 4
        for (int r0 = 0; r0 < 16; r0++) {
            int r = warp * 16 + r0;
            float4 a = x4[r * 64 + lane], b = x4[r * 64 + 32 + lane];
            float s = a.x + a.y + a.z + a.w + b.x + b.y + b.z + b.w;
            float q = a.x * a.x + a.y * a.y + a.z * a.z + a.w * a.w +
                      b.x * b.x + b.y * b.y + b.z * b.z + b.w * b.w;
            #pragma unroll
            for (int m = 16; m; m >>= 1) {
                s += __shfl_xor_sync(0xffffffffu, s, m);
                q += __shfl_xor_sync(0xffffffffu, q, m);
            }
            if (lane == 0) {
                float mean = s * (1.0f / 256.0f);
                float var = q * (1.0f / 256.0f) - mean * mean;
                sstat[r] = make_float2(mean, rsqrtf(var + 1e-5f));
            }
        }
    }

    unsigned long long acc[8][4];
    #pragma unroll
    for (int r = 0; r < 8; r++)
        #pragma unroll
        for (int c = 0; c < 4; c++) acc[r][c] = 0ull;

    int tx = tid & 15, ty = tid >> 4;             // 16x16 thread grid, 8x8 tiles
    int aR = tid >> 2, aK = tid & 3;              // A fill: rows aR, aR+64 / quad aK
    int wK0 = tid >> 5, wK1 = wK0 + 8, wC = tid & 31;  // W fill rows

    // Prologue: load kt=0 into regs
    float4 nA0 = x4[aR * 64 + aK];
    float4 nA1 = x4[(aR + 64) * 64 + aK];
    float4 nW0 = w14[wK0 * 32 + wC];
    float4 nW1 = w14[wK1 * 32 + wC];
    float nG0 = __ldg(&lng[wK0]);
    float nG1 = __ldg(&lng[wK1]);

    __syncthreads();   // sstat ready; also before first store

    // store kt=0 into buf 0
    {
        int kk = aK * 4;
        as[0][kk + 0][aR] = nA0.x; as[0][kk + 1][aR] = nA0.y;
        as[0][kk + 2][aR] = nA0.z; as[0][kk + 3][aR] = nA0.w;
        as[0][kk + 0][aR + 64] = nA1.x; as[0][kk + 1][aR + 64] = nA1.y;
        as[0][kk + 2][aR + 64] = nA1.z; as[0][kk + 3][aR + 64] = nA1.w;
        float4 w0 = make_float4(nW0.x * nG0, nW0.y * nG0, nW0.z * nG0, nW0.w * nG0);
        float4 w1v = make_float4(nW1.x * nG1, nW1.y * nG1, nW1.z * nG1, nW1.w * nG1);
        reinterpret_cast<float4*>(ws[0][wK0])[wC] = w0;
        reinterpret_cast<float4*>(ws[0][wK1])[wC] = w1v;
    }
    __syncthreads();

    for (int kt = 0; kt < 16; kt++) {
        int cur = kt & 1;
        if (kt < 15) {
            int k0q = (kt + 1) * 4;
            nA0 = x4[aR * 64 + k0q + aK];
            nA1 = x4[(aR + 64) * 64 + k0q + aK];
            nW0 = w14[((kt + 1) * 16 + wK0) * 32 + wC];
            nW1 = w14[((kt + 1) * 16 + wK1) * 32 + wC];
            nG0 = __ldg(&lng[(kt + 1) * 16 + wK0]);
            nG1 = __ldg(&lng[(kt + 1) * 16 + wK1]);
        }
        #pragma unroll
        for (int kk = 0; kk < 16; kk++) {
            float4 a0 = *reinterpret_cast<const float4*>(&as[cur][kk][ty * 8]);
            float4 a1 = *reinterpret_cast<const float4*>(&as[cur][kk][ty * 8 + 4]);
            const unsigned long long* wq0 =
                reinterpret_cast<const unsigned long long*>(&ws[cur][kk][tx * 4]);
            const unsigned long long* wq1 =
                reinterpret_cast<const unsigned long long*>(&ws[cur][kk][64 + tx * 4]);
            unsigned long long bd0 = wq0[0], bd1 = wq0[1], bd2 = wq1[0], bd3 = wq1[1];
            unsigned long long ad[8] = {packdup(a0.x), packdup(a0.y), packdup(a0.z), packdup(a0.w),
                                        packdup(a1.x), packdup(a1.y), packdup(a1.z), packdup(a1.w)};
            #pragma unroll
            for (int r = 0; r < 8; r++) {
                acc[r][0] = fma2(ad[r], bd0, acc[r][0]);
                acc[r][1] = fma2(ad[r], bd1, acc[r][1]);
                acc[r][2] = fma2(ad[r], bd2, acc[r][2]);
                acc[r][3] = fma2(ad[r], bd3, acc[r][3]);
            }
        }
        if (kt < 15) {
            int nb = cur ^ 1;
            int kk = aK * 4;
            as[nb][kk + 0][aR] = nA0.x; as[nb][kk + 1][aR] = nA0.y;
            as[nb][kk + 2][aR] = nA0.z; as[nb][kk + 3][aR] = nA0.w;
            as[nb][kk + 0][aR + 64] = nA1.x; as[nb][kk + 1][aR + 64] = nA1.y;
            as[nb][kk + 2][aR + 64] = nA1.z; as[nb][kk + 3][aR + 64] = nA1.w;
            float4 w0 = make_float4(nW0.x * nG0, nW0.y * nG0, nW0.z * nG0, nW0.w * nG0);
            float4 w1v = make_float4(nW1.x * nG1, nW1.y * nG1, nW1.z * nG1, nW1.w * nG1);
            reinterpret_cast<float4*>(ws[nb][wK0])[wC] = w0;
            reinterpret_cast<float4*>(ws[nb][wK1])[wC] = w1v;
        }
        __syncthreads();
    }

    // Epilogue: apply folded LN (z = rs*acc + u - m*rs*t), scatter-add into pre1
    float4 u0 = *reinterpret_cast<const float4*>(&g_u[tx * 4]);
    float4 u1 = *reinterpret_cast<const float4*>(&g_u[64 + tx * 4]);
    float4 t0 = *reinterpret_cast<const float4*>(&g_t[tx * 4]);
    float4 t1 = *reinterpret_cast<const float4*>(&g_t[64 + tx * 4]);
    const int* idxp = indices + t * NN_;
    #pragma unroll
    for (int r = 0; r < 8; r++) {
        float2 st = sstat[ty * 8 + r];
        float rs = st.y, mrs = st.x * st.y;
        int i = iBase + ty * 8 + r;
        int slot = idxp[i];
        float* dst = g_pre1 + ((size_t)t * NS_ + slot) * H_;
        float f0, f1, f2, f3, f4, f5, f6, f7;
        unpack2(acc[r][0], f0, f1);
        unpack2(acc[r][1], f2, f3);
        unpack2(acc[r][2], f4, f5);
        unpack2(acc[r][3], f6, f7);
        f0 = rs * f0 + u0.x - mrs * t0.x;
        f1 = rs * f1 + u0.y - mrs * t0.y;
        f2 = rs * f2 + u0.z - mrs * t0.z;
        f3 = rs * f3 + u0.w - mrs * t0.w;
        f4 = rs * f4 + u1.x - mrs * t1.x;
        f5 = rs * f5 + u1.y - mrs * t1.y;
        f6 = rs * f6 + u1.z - mrs * t1.z;
        f7 = rs * f7 + u1.w - mrs * t1.w;
        red4(dst + tx * 4, f0, f1, f2, f3);
        red4(dst + 64 + tx * 4, f4, f5, f6, f7);
    }
}

// ---------------------------------------------------------------------------
// K3: dense streaming gelu-sum over pre1. Zero rows (warp ballot) skip the
//     gelu math entirely — their contribution is zc * gelu(b1), added once.
//     Touched rows get gelu and a zeroing store to restore the invariant.
// ---------------------------------------------------------------------------
__global__ void __launch_bounds__(256) k_chunk(const float* __restrict__ b1) {
    __shared__ float part[8][128];
    int tid = threadIdx.x;
    int warp = tid >> 5, lane = tid & 31;

    float4 b1v = reinterpret_cast<const float4*>(b1)[lane];
    float4 acc = make_float4(0.f, 0.f, 0.f, 0.f);
    float4 z4 = make_float4(0.f, 0.f, 0.f, 0.f);
    int zc = 0;

    // block covers slots [blockIdx.x*256, +256) of the flat T*NS slot space
    float4* base = reinterpret_cast<float4*>(g_pre1) + ((size_t)blockIdx.x * 256 + warp * 32) * 32;

    #pragma unroll
    for (int i0 = 0; i0 < 32; i0 += 4) {
        float4 v0 = base[(i0 + 0) * 32 + lane];
        float4 v1 = base[(i0 + 1) * 32 + lane];
        float4 v2 = base[(i0 + 2) * 32 + lane];
        float4 v3 = base[(i0 + 3) * 32 + lane];
        #pragma unroll
        for (int u = 0; u < 4; u++) {
            float4 v = (u == 0) ? v0 : (u == 1) ? v1 : (u == 2) ? v2 : v3;
            bool nz = (v.x != 0.f) | (v.y != 0.f) | (v.z != 0.f) | (v.w != 0.f);
            unsigned m = __ballot_sync(0xffffffffu, nz);
            if (m) {                                   // warp-uniform branch
                acc.x += geluf(v.x + b1v.x);
                acc.y += geluf(v.y + b1v.y);
                acc.z += geluf(v.z + b1v.z);
                acc.w += geluf(v.w + b1v.w);
                base[(i0 + u) * 32 + lane] = z4;       // restore invariant
            } else {
                zc++;                                  // zero row: analytic gelu(b1)
            }
        }
    }

    float fzc = (float)zc;
    part[warp][lane * 4 + 0] = acc.x + fzc * geluf(b1v.x);
    part[warp][lane * 4 + 1] = acc.y + fzc * geluf(b1v.y);
    part[warp][lane * 4 + 2] = acc.z + fzc * geluf(b1v.z);
    part[warp][lane * 4 + 3] = acc.w + fzc * geluf(b1v.w);
    __syncthreads();
    if (tid < 128) {
        float s = 0.f;
        #pragma unroll
        for (int w = 0; w < 8; w++) s += part[w][tid];
        g_Spart[blockIdx.x * 128 + tid] = s;
    }
}

// ---------------------------------------------------------------------------
// K4: per t: reduce partials -> S ; comp = S@w2 + CHUNK*b2 ; LN(1024) ;
//     per-chunk LN(64) -> g_t2
// ---------------------------------------------------------------------------
__global__ void k_lnf(const float* __restrict__ w2, const float* __restrict__ b2,
                      const float* __restrict__ lnfg, const float* __restrict__ lnfb,
                      const float* __restrict__ lndg, const float* __restrict__ lndb) {
    __shared__ float sS[CL_ * H_];          // 2048
    __shared__ float sc[CL_ * CD_];         // 1024
    __shared__ float redbuf[16];
    __shared__ float bcast[2];

    int tid = threadIdx.x, lane = tid & 31, warp = tid >> 5;
    int t = blockIdx.x;

    // Reduce 8 sub-block partials per (chunk, k)
    const float* sp = g_Spart + t * CL_ * 8 * H_;
    for (int o = tid; o < CL_ * H_; o += 256) {
        int c = o >> 7, k = o & 127;
        float s = 0.f;
        #pragma unroll
        for (int sub = 0; sub < 8; sub++) s += sp[(c * 8 + sub) * H_ + k];
        sS[o] = s;
    }
    __syncthreads();

    // comp = S @ w2 + CHUNK*b2
    {
        int jj = tid & 63, cg = tid >> 6;   // thread covers chunks cg, cg+4, cg+8, cg+12
        float a0 = 0.f, a1 = 0.f, a2 = 0.f, a3 = 0.f;
        for (int k = 0; k < H_; k++) {
            float w = w2[k * 64 + jj];
            a0 += sS[(cg) * H_ + k] * w;
            a1 += sS[(cg + 4) * H_ + k] * w;
            a2 += sS[(cg + 8) * H_ + k] * w;
            a3 += sS[(cg + 12) * H_ + k] * w;
        }
        float bb = (float)CHUNK_ * b2[jj];
        sc[(cg) * 64 + jj] = a0 + bb;
        sc[(cg + 4) * 64 + jj] = a1 + bb;
        sc[(cg + 8) * 64 + jj] = a2 + bb;
        sc[(cg + 12) * 64 + jj] = a3 + bb;
    }
    __syncthreads();

    // LN over 1024 (lnf)
    float s = 0.f, q = 0.f;
    for (int o = tid; o < 1024; o += 256) { float v = sc[o]; s += v; q += v * v; }
    #pragma unroll
    for (int m = 16; m; m >>= 1) {
        s += __shfl_xor_sync(0xffffffffu, s, m);
        q += __shfl_xor_sync(0xffffffffu, q, m);
    }
    if (lane == 0) { redbuf[warp] = s; redbuf[8 + warp] = q; }
    __syncthreads();
    if (tid == 0) {
        float S2 = 0.f, Q2 = 0.f;
        #pragma unroll
        for (int w = 0; w < 8; w++) { S2 += redbuf[w]; Q2 += redbuf[8 + w]; }
        float m = S2 * (1.0f / 1024.0f);
        float var = Q2 * (1.0f / 1024.0f) - m * m;
        bcast[0] = m;
        bcast[1] = rsqrtf(var + 1e-5f);
    }
    __syncthreads();
    float m1 = bcast[0], rs1 = bcast[1];
    for (int o = tid; o < 1024; o += 256) sc[o] = (sc[o] - m1) * rs1 * lnfg[o] + lnfb[o];
    __syncthreads();

    // per-chunk LN over 64 (lnd) — each warp handles 2 chunks; write g_t2
    #pragma unroll
    for (int gi = 0; gi < 2; gi++) {
        int g = warp * 2 + gi;
        float v0 = sc[g * 64 + lane], v1 = sc[g * 64 + 32 + lane];
        float gs = v0 + v1, gq = v0 * v0 + v1 * v1;
        #pragma unroll
        for (int mm = 16; mm; mm >>= 1) {
            gs += __shfl_xor_sync(0xffffffffu, gs, mm);
            gq += __shfl_xor_sync(0xffffffffu, gq, mm);
        }
        float gm = gs * (1.0f / 64.0f);
        float gv = gq * (1.0f / 64.0f) - gm * gm;
        float grs = rsqrtf(gv + 1e-5f);
        g_t2[t * 1024 + g * 64 + lane] = (v0 - gm) * grs * lndg[lane] + lndb[lane];
        g_t2[t * 1024 + g * 64 + 32 + lane] =
            (v1 - gm) * grs * lndg[lane + 32] + lndb[lane + 32];
    }
}

// ---------------------------------------------------------------------------
// K5: decoder MLP, one block per (t, chunk): 64 -> gelu(128) -> 256
// ---------------------------------------------------------------------------
__global__ void k_dec(const float* __restrict__ dw1, const float* __restrict__ db1,
                      const float* __restrict__ dw2, const float* __restrict__ db2) {
    __shared__ float t2s[CD_];
    __shared__ float d1[H_];
    int tid = threadIdx.x;
    int row = blockIdx.x;                    // t*16 + c

    if (tid < CD_) t2s[tid] = g_t2[row * CD_ + tid];
    __syncthreads();

    if (tid < H_) {
        float a0 = 0.f, a1 = 0.f;
        #pragma unroll
        for (int j = 0; j < CD_; j += 2) {
            a0 += t2s[j] * __ldg(&dw1[j * H_ + tid]);
            a1 += t2s[j + 1] * __ldg(&dw1[(j + 1) * H_ + tid]);
        }
        d1[tid] = geluf(a0 + a1 + db1[tid]);
    }
    __syncthreads();

    float o0 = 0.f, o1 = 0.f;
    #pragma unroll
    for (int k = 0; k < H_; k += 2) {
        o0 += d1[k] * __ldg(&dw2[k * D_ + tid]);
        o1 += d1[k + 1] * __ldg(&dw2[(k + 1) * D_ + tid]);
    }
    g_dec[row * D_ + tid] = o0 + o1 + db2[tid];
}

// ---------------------------------------------------------------------------
// K6: output gather (rows < 8192: broadcast decoded chunk row; else zeros)
// ---------------------------------------------------------------------------
__global__ void k_gather(const int* __restrict__ indices, float4* __restrict__ out) {
    int idx = blockIdx.x * 256 + threadIdx.x;   // over T*NT*64 float4s
    int r = idx >> 6, q = idx & 63;
    int t = r / NT_;
    int i = r - t * NT_;
    float4 v;
    if (i < NN_) {
        int c = indices[t * NN_ + i] >> 11;     // chunk = slot / 2048
        v = reinterpret_cast<const float4*>(g_dec)[(t * CL_ + c) * 64 + q];
    } else {
        v = make_float4(0.f, 0.f, 0.f, 0.f);
    }
    out[idx] = v;
}

extern "C" void kernel_launch(void* const* d_in, const int* in_sizes, int n_in,
                              void* d_out, int out_size) {
    const float* x    = (const float*)d_in[0];
    const int*   ind  = (const int*)d_in[1];
    const float* ln1g = (const float*)d_in[2];
    const float* ln1b = (const float*)d_in[3];
    const float* w1   = (const float*)d_in[4];
    const float* b1   = (const float*)d_in[5];
    const float* w2   = (const float*)d_in[6];
    const float* b2   = (const float*)d_in[7];
    const float* lnfg = (const float*)d_in[8];
    const float* lnfb = (const float*)d_in[9];
    const float* lndg = (const float*)d_in[10];
    const float* lndb = (const float*)d_in[11];
    const float* dw1  = (const float*)d_in[12];
    const float* db1  = (const float*)d_in[13];
    const float* dw2  = (const float*)d_in[14];
    const float* db2  = (const float*)d_in[15];

    k_prep<<<1, 128>>>(ln1g, ln1b, w1);                        // launch 1
    k_nop<<<1, 32>>>();                                        // launch 2
    k_nop<<<1, 32>>>();                                        // launch 3
    k_gemm<<<T_ * NN_ / 128, 256>>>(x, ind, ln1g, w1);         // launch 4 (profiled)
    k_chunk<<<T_ * NS_ / 256, 256>>>(b1);
    k_lnf<<<T_, 256>>>(w2, b2, lnfg, lnfb, lndg, lndb);
    k_dec<<<T_ * CL_, 256>>>(dw1, db1, dw2, db2);
    k_gather<<<(T_ * NT_ * 64) / 256, 256>>>(ind, (float4*)d_out);
}

// round 11
// speedup vs baseline: 2.0419x; 1.1527x over previous
#include <cuda_runtime.h>
#include <cuda_bf16.h>
#include <math.h>
#include <stdint.h>

#define T_ 8
#define NT_ 12288
#define D_ 256
#define NN_ 8192
#define NS_ 32768
#define CL_ 16
#define CD_ 64
#define CHUNK_ 2048
#define H_ 128

// dynamic smem layout for k_gemm_mma
#define SM_BH 0
#define SM_BL 67584
#define SM_STAT 135168
#define SM_U 136192
#define SM_T 136704
#define SM_SLOT 137216
#define SM_TOTAL 137728

// Scratch (device globals; zero-initialized at load; pre1 invariant restored by k_chunk)
__device__ __align__(16) float g_pre1[(size_t)T_ * NS_ * H_];   // scatter accumulator (134 MB)
__device__ float g_u[H_];                                       // sum_k beta_k * w1[k][c]
__device__ float g_t[H_];                                       // sum_k gamma_k * w1[k][c]
__device__ __align__(16) __nv_bfloat16 g_w1h[H_ * D_];          // (gamma*w1)^T hi bf16 [n][k]
__device__ __align__(16) __nv_bfloat16 g_w1l[H_ * D_];          // (gamma*w1)^T lo bf16 [n][k]
__device__ __align__(16) float g_Spart[T_ * CL_ * 8 * H_];      // per-subblock gelu partial sums
__device__ float g_t2[T_ * CL_ * CD_];                          // post-LN chunk vectors
__device__ float g_dec[T_ * CL_ * D_];                          // decoded vectors

__device__ __forceinline__ float geluf(float v) {
    return 0.5f * v * (1.0f + erff(v * 0.70710678118654752440f));
}
__device__ __forceinline__ void red2(float* p, float a, float b) {
    asm volatile("red.global.add.v2.f32 [%0], {%1,%2};"
                 :: "l"(p), "f"(a), "f"(b) : "memory");
}
// bf16 HMMA m16n8k16, fp32 accum (legal on base compute_103 target)
__device__ __forceinline__ void mma_bf16(float* c, const uint32_t* a, const uint32_t* b) {
    asm volatile(
        "mma.sync.aligned.m16n8k16.row.col.f32.bf16.bf16.f32 "
        "{%0,%1,%2,%3}, {%4,%5,%6,%7}, {%8,%9}, {%0,%1,%2,%3};"
        : "+f"(c[0]), "+f"(c[1]), "+f"(c[2]), "+f"(c[3])
        : "r"(a[0]), "r"(a[1]), "r"(a[2]), "r"(a[3]), "r"(b[0]), "r"(b[1]));
}
// split a float2 into packed bf16x2 hi and lo (x in low half)
__device__ __forceinline__ void split2(float2 p, uint32_t& hi, uint32_t& lo) {
    __nv_bfloat162 h = __floats2bfloat162_rn(p.x, p.y);
    __nv_bfloat162 l = __floats2bfloat162_rn(p.x - __bfloat162float(h.x),
                                             p.y - __bfloat162float(h.y));
    hi = *reinterpret_cast<uint32_t*>(&h);
    lo = *reinterpret_cast<uint32_t*>(&l);
}

// no-op: launch-slot spacer so k_gemm_mma lands in ncu's profiled (4th) launch
__global__ void k_nop() {}

// ---------------------------------------------------------------------------
// K0a: B = (gamma .* w1)^T as bf16 hi/lo, plain [n=128][k=256] row-major
// ---------------------------------------------------------------------------
__global__ void k_prep_w(const float* __restrict__ lng, const float* __restrict__ w1) {
    int e0 = (blockIdx.x * 256 + threadIdx.x) * 4;   // 32768 elems, 4 per thread
    int n = e0 >> 8;
    #pragma unroll
    for (int j = 0; j < 4; j++) {
        int k = (e0 & 255) + j;
        float val = __ldg(&lng[k]) * __ldg(&w1[k * H_ + n]);
        __nv_bfloat16 h = __float2bfloat16(val);
        __nv_bfloat16 l = __float2bfloat16(val - __bfloat162float(h));
        g_w1h[n * D_ + k] = h;
        g_w1l[n * D_ + k] = l;
    }
}

// ---------------------------------------------------------------------------
// K0b: u[c] = sum_k beta_k w1[k][c];  t[c] = sum_k gamma_k w1[k][c]
// ---------------------------------------------------------------------------
__global__ void k_prep_ut(const float* __restrict__ lng, const float* __restrict__ lnb,
                          const float* __restrict__ w1) {
    int c = threadIdx.x;   // 128
    float uu = 0.f, tt = 0.f;
    #pragma unroll 8
    for (int k = 0; k < D_; k++) {
        float w = __ldg(&w1[k * H_ + c]);
        uu += __ldg(&lnb[k]) * w;
        tt += __ldg(&lng[k]) * w;
    }
    g_u[c] = uu;
    g_t[c] = tt;
}

// ---------------------------------------------------------------------------
// K2: HMMA GEMM1. Block = 128 rows x 128 cols x K=256; 8 warps, each warp
//     owns 16 rows x 128 cols. bf16-split fp32 emulation (Ah*Wh+Ah*Wl+Al*Wh).
//     A fragments straight from global (convert in regs); B staged in smem
//     (stride-264 padding -> conflict-free frag loads). LN folded in epilogue;
//     red.v2 scatter into pre1[slot].
// ---------------------------------------------------------------------------
__global__ void __launch_bounds__(256, 1)
k_gemm_mma(const float* __restrict__ x, const int* __restrict__ indices) {
    extern __shared__ __align__(16) char dsm[];
    __nv_bfloat16* bh = reinterpret_cast<__nv_bfloat16*>(dsm + SM_BH);
    __nv_bfloat16* bl = reinterpret_cast<__nv_bfloat16*>(dsm + SM_BL);
    float2* sstat = reinterpret_cast<float2*>(dsm + SM_STAT);
    float* su = reinterpret_cast<float*>(dsm + SM_U);
    float* stt = reinterpret_cast<float*>(dsm + SM_T);
    int* sslot = reinterpret_cast<int*>(dsm + SM_SLOT);

    int tid = threadIdx.x;
    int warp = tid >> 5, lane = tid & 31;
    int gid = lane >> 2, tg = lane & 3;
    int rowBase = blockIdx.x * 128;
    int t = rowBase >> 13;
    int iBase = rowBase & (NN_ - 1);

    const float4* x4 = reinterpret_cast<const float4*>(x) + ((size_t)t * NT_ + iBase) * (D_ / 4);

    // Phase 0a: stats for warp's 16 rows (these are exactly the rows it MMAs)
    #pragma unroll 4
    for (int r0 = 0; r0 < 16; r0++) {
        int r = warp * 16 + r0;
        float4 a = x4[r * 64 + lane], b = x4[r * 64 + 32 + lane];
        float s = a.x + a.y + a.z + a.w + b.x + b.y + b.z + b.w;
        float q = a.x * a.x + a.y * a.y + a.z * a.z + a.w * a.w +
                  b.x * b.x + b.y * b.y + b.z * b.z + b.w * b.w;
        #pragma unroll
        for (int m = 16; m; m >>= 1) {
            s += __shfl_xor_sync(0xffffffffu, s, m);
            q += __shfl_xor_sync(0xffffffffu, q, m);
        }
        if (lane == 0) {
            float mean = s * (1.0f / 256.0f);
            float var = q * (1.0f / 256.0f) - mean * mean;
            sstat[r] = make_float2(mean, rsqrtf(var + 1e-5f));
        }
    }
    // Phase 0b: stage B hi/lo into smem (stride 264 bf16 = 528 B rows)
    {
        const uint4* sh = reinterpret_cast<const uint4*>(g_w1h);
        const uint4* sl = reinterpret_cast<const uint4*>(g_w1l);
        #pragma unroll
        for (int i = tid; i < 4096; i += 256) {
            int n = i >> 5, j = i & 31;
            *reinterpret_cast<uint4*>(dsm + SM_BH + n * 528 + j * 16) = sh[i];
            *reinterpret_cast<uint4*>(dsm + SM_BL + n * 528 + j * 16) = sl[i];
        }
    }
    if (tid < 128) {
        su[tid] = g_u[tid];
        stt[tid] = g_t[tid];
        sslot[tid] = __ldg(&indices[t * NN_ + iBase + tid]);
    }
    __syncthreads();

    // Mainloop: no syncs; A from global with in-reg bf16 split
    const float2* xr0 = reinterpret_cast<const float2*>(x)
                      + ((size_t)t * NT_ + iBase + warp * 16 + gid) * 128;
    const float2* xr8 = xr0 + 8 * 128;

    float acc[16][4];
    #pragma unroll
    for (int nt = 0; nt < 16; nt++)
        #pragma unroll
        for (int c = 0; c < 4; c++) acc[nt][c] = 0.f;

    #pragma unroll 2
    for (int ks = 0; ks < 16; ks++) {
        float2 p00 = xr0[ks * 8 + tg], p08 = xr0[ks * 8 + tg + 4];
        float2 p80 = xr8[ks * 8 + tg], p88 = xr8[ks * 8 + tg + 4];
        uint32_t ah[4], al[4];
        split2(p00, ah[0], al[0]);
        split2(p80, ah[1], al[1]);
        split2(p08, ah[2], al[2]);
        split2(p88, ah[3], al[3]);
        int kb = ks * 16 + 2 * tg;
        #pragma unroll
        for (int nt = 0; nt < 16; nt++) {
            int n = nt * 8 + gid;
            uint32_t bhf[2], blf[2];
            bhf[0] = *reinterpret_cast<const uint32_t*>(bh + n * 264 + kb);
            bhf[1] = *reinterpret_cast<const uint32_t*>(bh + n * 264 + kb + 8);
            blf[0] = *reinterpret_cast<const uint32_t*>(bl + n * 264 + kb);
            blf[1] = *reinterpret_cast<const uint32_t*>(bl + n * 264 + kb + 8);
            mma_bf16(acc[nt], ah, bhf);
            mma_bf16(acc[nt], ah, blf);
            mma_bf16(acc[nt], al, bhf);
        }
    }

    // Epilogue: fold LN (z = rs*acc + u - m*rs*t), red.v2 scatter into pre1
    {
        int r0 = warp * 16 + gid, r1 = r0 + 8;
        float2 s0 = sstat[r0], s1 = sstat[r1];
        float rs0 = s0.y, mr0 = s0.x * s0.y;
        float rs1 = s1.y, mr1 = s1.x * s1.y;
        float* d0 = g_pre1 + ((size_t)t * NS_ + sslot[r0]) * H_;
        float* d1 = g_pre1 + ((size_t)t * NS_ + sslot[r1]) * H_;
        #pragma unroll
        for (int nt = 0; nt < 16; nt++) {
            int c = nt * 8 + 2 * tg;
            float u0 = su[c], u1 = su[c + 1];
            float t0 = stt[c], t1 = stt[c + 1];
            red2(d0 + c, rs0 * acc[nt][0] + u0 - mr0 * t0,
                         rs0 * acc[nt][1] + u1 - mr0 * t1);
            red2(d1 + c, rs1 * acc[nt][2] + u0 - mr1 * t0,
                         rs1 * acc[nt][3] + u1 - mr1 * t1);
        }
    }
}

// ---------------------------------------------------------------------------
// K3: dense streaming gelu-sum over pre1; zero rows (warp ballot) skip gelu
//     (contribution = zc * gelu(b1)); touched rows are re-zeroed.
// ---------------------------------------------------------------------------
__global__ void __launch_bounds__(256) k_chunk(const float* __restrict__ b1) {
    __shared__ float part[8][128];
    int tid = threadIdx.x;
    int warp = tid >> 5, lane = tid & 31;

    float4 b1v = reinterpret_cast<const float4*>(b1)[lane];
    float4 acc = make_float4(0.f, 0.f, 0.f, 0.f);
    float4 z4 = make_float4(0.f, 0.f, 0.f, 0.f);
    int zc = 0;

    float4* basep = reinterpret_cast<float4*>(g_pre1) + ((size_t)blockIdx.x * 256 + warp * 32) * 32;

    #pragma unroll
    for (int i0 = 0; i0 < 32; i0 += 4) {
        float4 v0 = basep[(i0 + 0) * 32 + lane];
        float4 v1 = basep[(i0 + 1) * 32 + lane];
        float4 v2 = basep[(i0 + 2) * 32 + lane];
        float4 v3 = basep[(i0 + 3) * 32 + lane];
        #pragma unroll
        for (int u = 0; u < 4; u++) {
            float4 v = (u == 0) ? v0 : (u == 1) ? v1 : (u == 2) ? v2 : v3;
            bool nz = (v.x != 0.f) | (v.y != 0.f) | (v.z != 0.f) | (v.w != 0.f);
            unsigned m = __ballot_sync(0xffffffffu, nz);
            if (m) {
                acc.x += geluf(v.x + b1v.x);
                acc.y += geluf(v.y + b1v.y);
                acc.z += geluf(v.z + b1v.z);
                acc.w += geluf(v.w + b1v.w);
                basep[(i0 + u) * 32 + lane] = z4;
            } else {
                zc++;
            }
        }
    }

    float fzc = (float)zc;
    part[warp][lane * 4 + 0] = acc.x + fzc * geluf(b1v.x);
    part[warp][lane * 4 + 1] = acc.y + fzc * geluf(b1v.y);
    part[warp][lane * 4 + 2] = acc.z + fzc * geluf(b1v.z);
    part[warp][lane * 4 + 3] = acc.w + fzc * geluf(b1v.w);
    __syncthreads();
    if (tid < 128) {
        float s = 0.f;
        #pragma unroll
        for (int w = 0; w < 8; w++) s += part[w][tid];
        g_Spart[blockIdx.x * 128 + tid] = s;
    }
}

// ---------------------------------------------------------------------------
// K4: per t: reduce partials -> S ; comp = S@w2 + CHUNK*b2 ; LN(1024) ;
//     per-chunk LN(64) -> g_t2
// ---------------------------------------------------------------------------
__global__ void k_lnf(const float* __restrict__ w2, const float* __restrict__ b2,
                      const float* __restrict__ lnfg, const float* __restrict__ lnfb,
                      const float* __restrict__ lndg, const float* __restrict__ lndb) {
    __shared__ float sS[CL_ * H_];
    __shared__ float sc[CL_ * CD_];
    __shared__ float redbuf[16];
    __shared__ float bcast[2];

    int tid = threadIdx.x, lane = tid & 31, warp = tid >> 5;
    int t = blockIdx.x;

    const float* sp = g_Spart + t * CL_ * 8 * H_;
    for (int o = tid; o < CL_ * H_; o += 256) {
        int c = o >> 7, k = o & 127;
        float s = 0.f;
        #pragma unroll
        for (int sub = 0; sub < 8; sub++) s += sp[(c * 8 + sub) * H_ + k];
        sS[o] = s;
    }
    __syncthreads();

    {
        int jj = tid & 63, cg = tid >> 6;
        float a0 = 0.f, a1 = 0.f, a2 = 0.f, a3 = 0.f;
        for (int k = 0; k < H_; k++) {
            float w = w2[k * 64 + jj];
            a0 += sS[(cg) * H_ + k] * w;
            a1 += sS[(cg + 4) * H_ + k] * w;
            a2 += sS[(cg + 8) * H_ + k] * w;
            a3 += sS[(cg + 12) * H_ + k] * w;
        }
        float bb = (float)CHUNK_ * b2[jj];
        sc[(cg) * 64 + jj] = a0 + bb;
        sc[(cg + 4) * 64 + jj] = a1 + bb;
        sc[(cg + 8) * 64 + jj] = a2 + bb;
        sc[(cg + 12) * 64 + jj] = a3 + bb;
    }
    __syncthreads();

    float s = 0.f, q = 0.f;
    for (int o = tid; o < 1024; o += 256) { float v = sc[o]; s += v; q += v * v; }
    #pragma unroll
    for (int m = 16; m; m >>= 1) {
        s += __shfl_xor_sync(0xffffffffu, s, m);
        q += __shfl_xor_sync(0xffffffffu, q, m);
    }
    if (lane == 0) { redbuf[warp] = s; redbuf[8 + warp] = q; }
    __syncthreads();
    if (tid == 0) {
        float S2 = 0.f, Q2 = 0.f;
        #pragma unroll
        for (int w = 0; w < 8; w++) { S2 += redbuf[w]; Q2 += redbuf[8 + w]; }
        float m = S2 * (1.0f / 1024.0f);
        float var = Q2 * (1.0f / 1024.0f) - m * m;
        bcast[0] = m;
        bcast[1] = rsqrtf(var + 1e-5f);
    }
    __syncthreads();
    float m1 = bcast[0], rs1 = bcast[1];
    for (int o = tid; o < 1024; o += 256) sc[o] = (sc[o] - m1) * rs1 * lnfg[o] + lnfb[o];
    __syncthreads();

    #pragma unroll
    for (int gi = 0; gi < 2; gi++) {
        int g = warp * 2 + gi;
        float v0 = sc[g * 64 + lane], v1 = sc[g * 64 + 32 + lane];
        float gs = v0 + v1, gq = v0 * v0 + v1 * v1;
        #pragma unroll
        for (int mm = 16; mm; mm >>= 1) {
            gs += __shfl_xor_sync(0xffffffffu, gs, mm);
            gq += __shfl_xor_sync(0xffffffffu, gq, mm);
        }
        float gm = gs * (1.0f / 64.0f);
        float gv = gq * (1.0f / 64.0f) - gm * gm;
        float grs = rsqrtf(gv + 1e-5f);
        g_t2[t * 1024 + g * 64 + lane] = (v0 - gm) * grs * lndg[lane] + lndb[lane];
        g_t2[t * 1024 + g * 64 + 32 + lane] =
            (v1 - gm) * grs * lndg[lane + 32] + lndb[lane + 32];
    }
}

// ---------------------------------------------------------------------------
// K5: decoder MLP, one block per (t, chunk): 64 -> gelu(128) -> 256
// ---------------------------------------------------------------------------
__global__ void k_dec(const float* __restrict__ dw1, const float* __restrict__ db1,
                      const float* __restrict__ dw2, const float* __restrict__ db2) {
    __shared__ float t2s[CD_];
    __shared__ float d1[H_];
    int tid = threadIdx.x;
    int row = blockIdx.x;

    if (tid < CD_) t2s[tid] = g_t2[row * CD_ + tid];
    __syncthreads();

    if (tid < H_) {
        float a0 = 0.f, a1 = 0.f;
        #pragma unroll
        for (int j = 0; j < CD_; j += 2) {
            a0 += t2s[j] * __ldg(&dw1[j * H_ + tid]);
            a1 += t2s[j + 1] * __ldg(&dw1[(j + 1) * H_ + tid]);
        }
        d1[tid] = geluf(a0 + a1 + db1[tid]);
    }
    __syncthreads();

    float o0 = 0.f, o1 = 0.f;
    #pragma unroll
    for (int k = 0; k < H_; k += 2) {
        o0 += d1[k] * __ldg(&dw2[k * D_ + tid]);
        o1 += d1[k + 1] * __ldg(&dw2[(k + 1) * D_ + tid]);
    }
    g_dec[row * D_ + tid] = o0 + o1 + db2[tid];
}

// ---------------------------------------------------------------------------
// K6: output gather (rows < 8192: broadcast decoded chunk row; else zeros)
// ---------------------------------------------------------------------------
__global__ void k_gather(const int* __restrict__ indices, float4* __restrict__ out) {
    int idx = blockIdx.x * 256 + threadIdx.x;
    int r = idx >> 6, q = idx & 63;
    int t = r / NT_;
    int i = r - t * NT_;
    float4 v;
    if (i < NN_) {
        int c = indices[t * NN_ + i] >> 11;
        v = reinterpret_cast<const float4*>(g_dec)[(t * CL_ + c) * 64 + q];
    } else {
        v = make_float4(0.f, 0.f, 0.f, 0.f);
    }
    out[idx] = v;
}

extern "C" void kernel_launch(void* const* d_in, const int* in_sizes, int n_in,
                              void* d_out, int out_size) {
    const float* x    = (const float*)d_in[0];
    const int*   ind  = (const int*)d_in[1];
    const float* ln1g = (const float*)d_in[2];
    const float* ln1b = (const float*)d_in[3];
    const float* w1   = (const float*)d_in[4];
    const float* b1   = (const float*)d_in[5];
    const float* w2   = (const float*)d_in[6];
    const float* b2   = (const float*)d_in[7];
    const float* lnfg = (const float*)d_in[8];
    const float* lnfb = (const float*)d_in[9];
    const float* lndg = (const float*)d_in[10];
    const float* lndb = (const float*)d_in[11];
    const float* dw1  = (const float*)d_in[12];
    const float* db1  = (const float*)d_in[13];
    const float* dw2  = (const float*)d_in[14];
    const float* db2  = (const float*)d_in[15];

    cudaFuncSetAttribute(k_gemm_mma, cudaFuncAttributeMaxDynamicSharedMemorySize, SM_TOTAL);

    k_prep_w<<<32, 256>>>(ln1g, w1);                               // launch 1
    k_prep_ut<<<1, 128>>>(ln1g, ln1b, w1);                         // launch 2
    k_nop<<<1, 32>>>();                                            // launch 3
    k_gemm_mma<<<T_ * NN_ / 128, 256, SM_TOTAL>>>(x, ind);         // launch 4 (profiled)
    k_chunk<<<T_ * NS_ / 256, 256>>>(b1);
    k_lnf<<<T_, 256>>>(w2, b2, lnfg, lnfb, lndg, lndb);
    k_dec<<<T_ * CL_, 256>>>(dw1, db1, dw2, db2);
    k_gather<<<(T_ * NT_ * 64) / 256, 256>>>(ind, (float4*)d_out);
}